// round 3
// baseline (speedup 1.0000x reference)
#include <cuda_runtime.h>
#include <cstdint>

#define NB_B   2
#define NB     512
#define LQ     64
#define KEYN   65
#define NH     8
#define HD     64
#define CDIM   512
#define NTOK   32768
#define BNB    (NB_B*NB)        // 1024 blocks total
#define MX     (NB_B*NTOK)      // 65536 x-rows
#define KVROWS (BNB*KEYN)       // 66560 kv-rows

// -------- device scratch (static, allocation-guard safe) --------
__device__ float g_q  [(size_t)MX*CDIM];
__device__ float g_k  [(size_t)KVROWS*CDIM];
__device__ float g_v  [(size_t)KVROWS*CDIM];
__device__ float g_bm [(size_t)BNB*CDIM];
__device__ float g_att[(size_t)MX*CDIM];
__device__ float g_biasadd[(size_t)BNB*4160];
__device__ float g_lew[(size_t)BNB*NH*4160];

// ================= block mean =================
__global__ void mean_kernel(const float* __restrict__ x) {
    int blk = blockIdx.x;                      // 0..1023 (b*512+nb)
    const float* base = x + (size_t)blk * (LQ * CDIM);
    for (int c = threadIdx.x; c < CDIM; c += blockDim.x) {
        float s = 0.f;
        #pragma unroll 8
        for (int l = 0; l < LQ; l++) s += base[(size_t)l * CDIM + c];
        g_bm[(size_t)blk * CDIM + c] = s * (1.f / 64.f);
    }
}

// ================= prep: fold mask into bias, precompute lew =================
__global__ void __launch_bounds__(256) prep_kernel(const float* __restrict__ edge,
                                                   const int* __restrict__ amask,
                                                   const float* __restrict__ eg_w,
                                                   const float* __restrict__ eg_b) {
    int bid = blockIdx.x;
    const float4* e4 = reinterpret_cast<const float4*>(edge) + (size_t)bid * 4160;
    const int* mk = amask + (size_t)bid * 4160;
    float w[NH][4], b[NH];
    #pragma unroll
    for (int h = 0; h < NH; h++) {
        w[h][0] = eg_w[h * 4 + 0]; w[h][1] = eg_w[h * 4 + 1];
        w[h][2] = eg_w[h * 4 + 2]; w[h][3] = eg_w[h * 4 + 3];
        b[h] = eg_b[h];
    }
    for (int i = threadIdx.x; i < 4160; i += 256) {
        int q = i / 65;
        int k = i - q * 65;
        float4 e = e4[i];
        if (k == 64 || k == q) e = make_float4(0.f, 0.f, 0.f, 1.f);
        bool m = (mk[i] != 0);
        g_biasadd[(size_t)bid * 4160 + i] = m ? e.w : -1e30f;
        #pragma unroll
        for (int h = 0; h < NH; h++) {
            float lv = e.x * w[h][0] + e.y * w[h][1] + e.z * w[h][2] + e.w * w[h][3] + b[h];
            g_lew[((size_t)bid * NH + h) * 4160 + i] = m ? lv : 0.f;
        }
    }
}

// ================= tf32 mma helpers =================
__device__ __forceinline__ float to_tf32(float x) {
    uint32_t u;
    asm("cvt.rna.tf32.f32 %0, %1;" : "=r"(u) : "f"(x));
    return __uint_as_float(u);
}

__device__ __forceinline__ void mma_tf32(float* c, const float* a, const float* b) {
    const uint32_t* A = reinterpret_cast<const uint32_t*>(a);
    const uint32_t* Bv = reinterpret_cast<const uint32_t*>(b);
    asm volatile(
        "mma.sync.aligned.m16n8k8.row.col.f32.tf32.tf32.f32 "
        "{%0,%1,%2,%3}, {%4,%5,%6,%7}, {%8,%9}, {%0,%1,%2,%3};\n"
        : "+f"(c[0]), "+f"(c[1]), "+f"(c[2]), "+f"(c[3])
        : "r"(A[0]), "r"(A[1]), "r"(A[2]), "r"(A[3]),
          "r"(Bv[0]), "r"(Bv[1]));
}

__device__ __forceinline__ void cp16(uint32_t smem_dst, const float* gmem_src) {
    asm volatile("cp.async.cg.shared.global [%0], [%1], 16;\n"
                 :: "r"(smem_dst), "l"(gmem_src));
}

// epilogue scatter
template <int MODE>
__device__ __forceinline__ void emit(int row, int col, float v, float* outp) {
    if (MODE == 0) {
        if (col < CDIM) {
            g_q[(size_t)row * CDIM + col] = v;
        } else {
            size_t kvr = (size_t)((row >> 6) * KEYN + (row & 63));
            if (col < 2 * CDIM) g_k[kvr * CDIM + (col - CDIM)] = v;
            else                g_v[kvr * CDIM + (col - 2 * CDIM)] = v;
        }
    } else if (MODE == 1) {
        size_t r = (size_t)row * KEYN + (KEYN - 1);
        if (col < CDIM) g_k[r * CDIM + col] = v;
        else            g_v[r * CDIM + (col - CDIM)] = v;
    } else {
        outp[(size_t)row * CDIM + col] = v;
    }
}

// ================= tf32 GEMM: C = A[M,512] * W[N,512]^T + bias =================
// 128x128x32 tiles, 256 threads = 8 warps (2x4), warp tile 64x32, mma m16n8k8
// cp.async 2-stage smem double buffering, 2 CTAs/SM
#define GEMM_TILE_FLOATS (128 * 36)
#define GEMM_SMEM_FLOATS (4 * GEMM_TILE_FLOATS)   // As[2] + Bs[2]
#define GEMM_SMEM_BYTES  (GEMM_SMEM_FLOATS * 4)   // 73728 B

template <int MODE>
__global__ void __launch_bounds__(256, 2) gemm_tf32(const float* __restrict__ Ain,
                                                    const float* __restrict__ W,
                                                    const float* __restrict__ bias,
                                                    float* __restrict__ outp) {
    const float* A = (MODE == 1) ? g_bm : (MODE == 2 ? g_att : Ain);
    extern __shared__ float gsm[];
    // layout: As[2][128][36], Bs[2][128][36]
    float* AsBase = gsm;
    float* BsBase = gsm + 2 * GEMM_TILE_FLOATS;
    uint32_t smem_u32 = (uint32_t)__cvta_generic_to_shared(gsm);

    int tid = threadIdx.x;
    int m0 = blockIdx.x * 128;
    int n0 = blockIdx.y * 128;
    int lr = tid >> 3;          // 0..31
    int lc = (tid & 7) * 4;     // 0..28

    int lane = tid & 31, wid = tid >> 5;
    int wm = wid >> 2, wn = wid & 3;   // warp grid 2 x 4
    int g = lane >> 2, t4 = lane & 3;

    float acc[4][4][4];
    #pragma unroll
    for (int mi = 0; mi < 4; mi++)
        #pragma unroll
        for (int ni = 0; ni < 4; ni++)
            #pragma unroll
            for (int r = 0; r < 4; r++) acc[mi][ni][r] = 0.f;

    // async-load one 128x32 k-tile of A and B into buffer `buf`
    auto load_tile = [&](int k0, int buf) {
        uint32_t a_base = smem_u32 + (uint32_t)((buf * 128 + lr) * 36 + lc) * 4u;
        uint32_t b_base = a_base + (uint32_t)(2 * GEMM_TILE_FLOATS) * 4u;
        #pragma unroll
        for (int i = 0; i < 4; i++) {
            cp16(a_base + (uint32_t)(32 * i * 36) * 4u,
                 &A[(size_t)(m0 + lr + 32 * i) * CDIM + k0 + lc]);
            cp16(b_base + (uint32_t)(32 * i * 36) * 4u,
                 &W[(size_t)(n0 + lr + 32 * i) * CDIM + k0 + lc]);
        }
    };

    load_tile(0, 0);
    asm volatile("cp.async.commit_group;\n");

    int buf = 0;
    for (int k0 = 0; k0 < CDIM; k0 += 32) {
        asm volatile("cp.async.wait_group 0;\n");
        __syncthreads();
        if (k0 + 32 < CDIM) {
            load_tile(k0 + 32, buf ^ 1);
            asm volatile("cp.async.commit_group;\n");
        }
        const float* As = AsBase + buf * GEMM_TILE_FLOATS;
        const float* Bs = BsBase + buf * GEMM_TILE_FLOATS;
        #pragma unroll
        for (int kk = 0; kk < 32; kk += 8) {
            float afr[4][4], bfr[4][2];
            #pragma unroll
            for (int mi = 0; mi < 4; mi++) {
                int row = wm * 64 + mi * 16 + g;
                afr[mi][0] = to_tf32(As[row * 36 + kk + t4]);
                afr[mi][1] = to_tf32(As[(row + 8) * 36 + kk + t4]);
                afr[mi][2] = to_tf32(As[row * 36 + kk + t4 + 4]);
                afr[mi][3] = to_tf32(As[(row + 8) * 36 + kk + t4 + 4]);
            }
            #pragma unroll
            for (int ni = 0; ni < 4; ni++) {
                int col = wn * 32 + ni * 8 + g;
                bfr[ni][0] = to_tf32(Bs[col * 36 + kk + t4]);
                bfr[ni][1] = to_tf32(Bs[col * 36 + kk + t4 + 4]);
            }
            #pragma unroll
            for (int mi = 0; mi < 4; mi++)
                #pragma unroll
                for (int ni = 0; ni < 4; ni++)
                    mma_tf32(acc[mi][ni], afr[mi], bfr[ni]);
        }
        buf ^= 1;
    }

    // epilogue
    #pragma unroll
    for (int mi = 0; mi < 4; mi++) {
        #pragma unroll
        for (int ni = 0; ni < 4; ni++) {
            int row = m0 + wm * 64 + mi * 16 + g;
            int col = n0 + wn * 32 + ni * 8 + t4 * 2;
            float b0 = bias[col], b1 = bias[col + 1];
            emit<MODE>(row,     col,     acc[mi][ni][0] + b0, outp);
            emit<MODE>(row,     col + 1, acc[mi][ni][1] + b1, outp);
            emit<MODE>(row + 8, col,     acc[mi][ni][2] + b0, outp);
            emit<MODE>(row + 8, col + 1, acc[mi][ni][3] + b1, outp);
        }
    }
}

// ================= attention =================
// one CTA per (b, blk): 256 threads, loop over 8 heads
// smem floats: biasadd 4160 | q 64*68 | k 72*68 | v 65*68 | comb 64*68
#define SM_Q_OFF    4160
#define SM_K_OFF    (SM_Q_OFF + 64 * 68)
#define SM_V_OFF    (SM_K_OFF + 72 * 68)
#define SM_CB_OFF   (SM_V_OFF + 65 * 68)
#define ATTN_SMEM_FLOATS (SM_CB_OFF + 64 * 68)
#define ATTN_SMEM_BYTES  (ATTN_SMEM_FLOATS * 4)   // ~88.7 KB -> 2 CTAs/SM

__global__ void __launch_bounds__(256, 2) attn_kernel() {
    extern __shared__ float sm[];
    float* ba_s = sm;                     // 4160 pre-masked additive bias
    float* q_s = sm + SM_Q_OFF;
    float* k_s = sm + SM_K_OFF;
    float* v_s = sm + SM_V_OFF;
    float* cb_s = sm + SM_CB_OFF;

    int bid = blockIdx.x;      // 0..1023
    int tid = threadIdx.x;

    for (int i = tid; i < 4160; i += 256)
        ba_s[i] = g_biasadd[(size_t)bid * 4160 + i];
    // zero-pad k rows 65..71 (read by cols>=65 lanes, results discarded)
    for (int i = tid; i < 7 * 68; i += 256) k_s[65 * 68 + i] = 0.f;

    int lane = tid & 31, warp = tid >> 5;
    int t8 = lane & 7, g2 = lane >> 3;
    int r0 = warp * 8 + g2 * 2;          // this lane handles rows r0, r0+1

    for (int h = 0; h < NH; h++) {
        __syncthreads();
        // load q/k/v head slices
        for (int f = tid; f < 64 * 16; f += 256) {
            int row = f >> 4, c4 = (f & 15) * 4;
            *reinterpret_cast<float4*>(&q_s[row * 68 + c4]) =
                *reinterpret_cast<const float4*>(&g_q[(size_t)(bid * 64 + row) * CDIM + h * 64 + c4]);
        }
        for (int f = tid; f < 65 * 16; f += 256) {
            int row = f / 16, c4 = (f & 15) * 4;
            size_t src = (size_t)(bid * 65 + row) * CDIM + h * 64 + c4;
            *reinterpret_cast<float4*>(&k_s[row * 68 + c4]) =
                *reinterpret_cast<const float4*>(&g_k[src]);
            *reinterpret_cast<float4*>(&v_s[row * 68 + c4]) =
                *reinterpret_cast<const float4*>(&g_v[src]);
        }
        __syncthreads();

        const float* lew_g = g_lew + ((size_t)bid * NH + h) * 4160;

        // ---- scores: rows r0,r0+1 x cols {t8+8j} ----
        float acc0[9], acc1[9];
        #pragma unroll
        for (int j = 0; j < 9; j++) { acc0[j] = 0.f; acc1[j] = 0.f; }
        #pragma unroll 4
        for (int d4 = 0; d4 < 16; d4++) {
            float4 qa = *reinterpret_cast<const float4*>(&q_s[r0 * 68 + d4 * 4]);
            float4 qb = *reinterpret_cast<const float4*>(&q_s[(r0 + 1) * 68 + d4 * 4]);
            #pragma unroll
            for (int j = 0; j < 9; j++) {
                float4 kv = *reinterpret_cast<const float4*>(&k_s[(t8 + 8 * j) * 68 + d4 * 4]);
                acc0[j] = fmaf(qa.x, kv.x, acc0[j]);
                acc0[j] = fmaf(qa.y, kv.y, acc0[j]);
                acc0[j] = fmaf(qa.z, kv.z, acc0[j]);
                acc0[j] = fmaf(qa.w, kv.w, acc0[j]);
                acc1[j] = fmaf(qb.x, kv.x, acc1[j]);
                acc1[j] = fmaf(qb.y, kv.y, acc1[j]);
                acc1[j] = fmaf(qb.z, kv.z, acc1[j]);
                acc1[j] = fmaf(qb.w, kv.w, acc1[j]);
            }
        }

        // ---- masked softmax + lew, write combined to smem ----
        #pragma unroll
        for (int rr = 0; rr < 2; rr++) {
            float* acc = rr ? acc1 : acc0;
            int row = r0 + rr;
            float mx = -1e30f;
            #pragma unroll
            for (int j = 0; j < 9; j++) {
                int col = t8 + 8 * j;
                if (col < 65) {
                    float s = acc[j] * 0.125f + ba_s[row * 65 + col];
                    acc[j] = s;
                    mx = fmaxf(mx, s);
                } else {
                    acc[j] = -3e30f;
                }
            }
            mx = fmaxf(mx, __shfl_xor_sync(0xffffffffu, mx, 1));
            mx = fmaxf(mx, __shfl_xor_sync(0xffffffffu, mx, 2));
            mx = fmaxf(mx, __shfl_xor_sync(0xffffffffu, mx, 4));
            float sum = 0.f;
            #pragma unroll
            for (int j = 0; j < 9; j++) {
                float p = __expf(acc[j] - mx);
                acc[j] = p;
                sum += p;
            }
            sum += __shfl_xor_sync(0xffffffffu, sum, 1);
            sum += __shfl_xor_sync(0xffffffffu, sum, 2);
            sum += __shfl_xor_sync(0xffffffffu, sum, 4);
            float inv = 1.f / sum;
            #pragma unroll
            for (int j = 0; j < 9; j++) {
                int col = t8 + 8 * j;
                if (col < 65) {
                    int idx = row * 65 + col;
                    cb_s[row * 68 + col] = acc[j] * inv + __ldg(&lew_g[idx]);
                }
            }
        }
        __syncwarp();

        // ---- AV: out[row, d in t8*8 .. t8*8+7] ----
        float o0[8], o1[8];
        #pragma unroll
        for (int j = 0; j < 8; j++) { o0[j] = 0.f; o1[j] = 0.f; }
        for (int k = 0; k < 65; k++) {
            float cv0 = cb_s[r0 * 68 + k];
            float cv1 = cb_s[(r0 + 1) * 68 + k];
            float4 va = *reinterpret_cast<const float4*>(&v_s[k * 68 + t8 * 8]);
            float4 vb = *reinterpret_cast<const float4*>(&v_s[k * 68 + t8 * 8 + 4]);
            o0[0] = fmaf(cv0, va.x, o0[0]); o0[1] = fmaf(cv0, va.y, o0[1]);
            o0[2] = fmaf(cv0, va.z, o0[2]); o0[3] = fmaf(cv0, va.w, o0[3]);
            o0[4] = fmaf(cv0, vb.x, o0[4]); o0[5] = fmaf(cv0, vb.y, o0[5]);
            o0[6] = fmaf(cv0, vb.z, o0[6]); o0[7] = fmaf(cv0, vb.w, o0[7]);
            o1[0] = fmaf(cv1, va.x, o1[0]); o1[1] = fmaf(cv1, va.y, o1[1]);
            o1[2] = fmaf(cv1, va.z, o1[2]); o1[3] = fmaf(cv1, va.w, o1[3]);
            o1[4] = fmaf(cv1, vb.x, o1[4]); o1[5] = fmaf(cv1, vb.y, o1[5]);
            o1[6] = fmaf(cv1, vb.z, o1[6]); o1[7] = fmaf(cv1, vb.w, o1[7]);
        }
        float* dst0 = g_att + (size_t)(bid * 64 + r0) * CDIM + h * 64 + t8 * 8;
        *reinterpret_cast<float4*>(dst0)     = make_float4(o0[0], o0[1], o0[2], o0[3]);
        *reinterpret_cast<float4*>(dst0 + 4) = make_float4(o0[4], o0[5], o0[6], o0[7]);
        float* dst1 = dst0 + CDIM;
        *reinterpret_cast<float4*>(dst1)     = make_float4(o1[0], o1[1], o1[2], o1[3]);
        *reinterpret_cast<float4*>(dst1 + 4) = make_float4(o1[4], o1[5], o1[6], o1[7]);
    }
}

// ================= host =================
extern "C" void kernel_launch(void* const* d_in, const int* in_sizes, int n_in,
                              void* d_out, int out_size) {
    (void)in_sizes; (void)n_in; (void)out_size;
    const float* x      = (const float*)d_in[0];
    const int*   amask  = (const int*)d_in[1];
    const float* edge   = (const float*)d_in[2];
    const float* qkv_w  = (const float*)d_in[3];
    const float* qkv_b  = (const float*)d_in[4];
    const float* proj_w = (const float*)d_in[5];
    const float* proj_b = (const float*)d_in[6];
    const float* eg_w   = (const float*)d_in[7];
    const float* eg_b   = (const float*)d_in[8];
    float* out = (float*)d_out;

    cudaFuncSetAttribute(attn_kernel, cudaFuncAttributeMaxDynamicSharedMemorySize, ATTN_SMEM_BYTES);
    cudaFuncSetAttribute(gemm_tf32<0>, cudaFuncAttributeMaxDynamicSharedMemorySize, GEMM_SMEM_BYTES);
    cudaFuncSetAttribute(gemm_tf32<1>, cudaFuncAttributeMaxDynamicSharedMemorySize, GEMM_SMEM_BYTES);
    cudaFuncSetAttribute(gemm_tf32<2>, cudaFuncAttributeMaxDynamicSharedMemorySize, GEMM_SMEM_BYTES);

    mean_kernel<<<BNB, 256>>>(x);
    prep_kernel<<<BNB, 256>>>(edge, amask, eg_w, eg_b);
    gemm_tf32<0><<<dim3(MX / 128, 1536 / 128), 256, GEMM_SMEM_BYTES>>>(x, qkv_w, qkv_b, nullptr);
    gemm_tf32<1><<<dim3(BNB / 128, 1024 / 128), 256, GEMM_SMEM_BYTES>>>(nullptr, qkv_w + (size_t)512 * 512, qkv_b + 512, nullptr);
    attn_kernel<<<BNB, 256, ATTN_SMEM_BYTES>>>();
    gemm_tf32<2><<<dim3(MX / 128, 512 / 128), 256, GEMM_SMEM_BYTES>>>(nullptr, proj_w, proj_b, out);
}

// round 5
// speedup vs baseline: 1.3141x; 1.3141x over previous
#include <cuda_runtime.h>
#include <cuda_fp16.h>
#include <cstdint>

#define NB_B   2
#define NB     512
#define LQ     64
#define KEYN   65
#define NH     8
#define HD     64
#define CDIM   512
#define NTOK   32768
#define BNB    (NB_B*NB)        // 1024 blocks total
#define MX     (NB_B*NTOK)      // 65536 x-rows
#define KVROWS (BNB*KEYN)       // 66560 kv-rows

// -------- device scratch (static, allocation-guard safe) --------
__device__ float  g_q  [(size_t)MX*CDIM];
__device__ float  g_k  [(size_t)KVROWS*CDIM];
__device__ float  g_v  [(size_t)KVROWS*CDIM];
__device__ float  g_biasadd[(size_t)BNB*4160];
__device__ float  g_lew[(size_t)BNB*NH*4160];
__device__ __half g_xh [(size_t)MX*CDIM];       // fp16 x
__device__ __half g_wqh[(size_t)3*CDIM*CDIM];   // fp16 qkv_w
__device__ __half g_wph[(size_t)CDIM*CDIM];     // fp16 proj_w
__device__ __half g_bmh[(size_t)BNB*CDIM];      // fp16 block means
__device__ __half g_atth[(size_t)MX*CDIM];      // fp16 attention output

// ================= fp32 -> fp16 conversion =================
__global__ void conv_h(const float4* __restrict__ src, __half2* __restrict__ dst, int n4) {
    int i = blockIdx.x * blockDim.x + threadIdx.x;
    if (i < n4) {
        float4 v = src[i];
        dst[2 * i]     = __floats2half2_rn(v.x, v.y);
        dst[2 * i + 1] = __floats2half2_rn(v.z, v.w);
    }
}

// ================= block mean (fp16 output; feeds gemm only) =================
__global__ void mean_kernel(const float* __restrict__ x) {
    int blk = blockIdx.x;
    const float* base = x + (size_t)blk * (LQ * CDIM);
    for (int c = threadIdx.x; c < CDIM; c += blockDim.x) {
        float s = 0.f;
        #pragma unroll 8
        for (int l = 0; l < LQ; l++) s += base[(size_t)l * CDIM + c];
        g_bmh[(size_t)blk * CDIM + c] = __float2half_rn(s * (1.f / 64.f));
    }
}

// ================= prep: fold mask into bias, precompute lew =================
__global__ void __launch_bounds__(256) prep_kernel(const float* __restrict__ edge,
                                                   const int* __restrict__ amask,
                                                   const float* __restrict__ eg_w,
                                                   const float* __restrict__ eg_b) {
    int bid = blockIdx.x;
    const float4* e4 = reinterpret_cast<const float4*>(edge) + (size_t)bid * 4160;
    const int* mk = amask + (size_t)bid * 4160;
    float w[NH][4], b[NH];
    #pragma unroll
    for (int h = 0; h < NH; h++) {
        w[h][0] = eg_w[h * 4 + 0]; w[h][1] = eg_w[h * 4 + 1];
        w[h][2] = eg_w[h * 4 + 2]; w[h][3] = eg_w[h * 4 + 3];
        b[h] = eg_b[h];
    }
    for (int i = threadIdx.x; i < 4160; i += 256) {
        int q = i / 65;
        int k = i - q * 65;
        float4 e = e4[i];
        if (k == 64 || k == q) e = make_float4(0.f, 0.f, 0.f, 1.f);
        bool m = (mk[i] != 0);
        g_biasadd[(size_t)bid * 4160 + i] = m ? e.w : -1e30f;
        #pragma unroll
        for (int h = 0; h < NH; h++) {
            float lv = e.x * w[h][0] + e.y * w[h][1] + e.z * w[h][2] + e.w * w[h][3] + b[h];
            g_lew[((size_t)bid * NH + h) * 4160 + i] = m ? lv : 0.f;
        }
    }
}

// ================= fp16 mma helpers =================
__device__ __forceinline__ void mma_f16(float* c, const uint32_t* a, const uint32_t* b) {
    asm volatile(
        "mma.sync.aligned.m16n8k16.row.col.f32.f16.f16.f32 "
        "{%0,%1,%2,%3}, {%4,%5,%6,%7}, {%8,%9}, {%0,%1,%2,%3};\n"
        : "+f"(c[0]), "+f"(c[1]), "+f"(c[2]), "+f"(c[3])
        : "r"(a[0]), "r"(a[1]), "r"(a[2]), "r"(a[3]),
          "r"(b[0]), "r"(b[1]));
}

__device__ __forceinline__ void cp16(uint32_t smem_dst, const __half* gmem_src) {
    asm volatile("cp.async.cg.shared.global [%0], [%1], 16;\n"
                 :: "r"(smem_dst), "l"(gmem_src));
}

// epilogue scatter
template <int MODE>
__device__ __forceinline__ void emit(int row, int col, float v, float* outp) {
    if (MODE == 0) {
        if (col < CDIM) {
            g_q[(size_t)row * CDIM + col] = v;
        } else {
            size_t kvr = (size_t)((row >> 6) * KEYN + (row & 63));
            if (col < 2 * CDIM) g_k[kvr * CDIM + (col - CDIM)] = v;
            else                g_v[kvr * CDIM + (col - 2 * CDIM)] = v;
        }
    } else if (MODE == 1) {
        size_t r = (size_t)row * KEYN + (KEYN - 1);
        if (col < CDIM) g_k[r * CDIM + col] = v;
        else            g_v[r * CDIM + (col - CDIM)] = v;
    } else {
        outp[(size_t)row * CDIM + col] = v;
    }
}

// ================= fp16 GEMM: C = A[M,512] * W[N,512]^T + bias =================
// 128x128 CTA tile, k-tile 64 halves, 2-stage cp.async double buffer.
// 8 warps (2x4), warp tile 64x32, mma m16n8k16.
// smem (halves): A[2][128][72], B[2][128][72] = 36864 halves = 73728 B -> 2 CTAs/SM
#define GH_STAGE  (128 * 72)          // halves per stage per tile
#define GH_B_OFF  (2 * GH_STAGE)      // B region start
#define GEMM_SMEM_BYTES (4 * GH_STAGE * 2)

template <int MODE>
__global__ void __launch_bounds__(256, 2) gemm_h(const __half* __restrict__ Ain,
                                                 const __half* __restrict__ W,
                                                 const float* __restrict__ bias,
                                                 float* __restrict__ outp) {
    const __half* A = (MODE == 1) ? g_bmh : (MODE == 2 ? g_atth : Ain);
    extern __shared__ __align__(16) __half hsm[];
    uint32_t smem_u32 = (uint32_t)__cvta_generic_to_shared(hsm);

    int tid = threadIdx.x;
    int n0 = blockIdx.x * 128;
    int m0 = blockIdx.y * 128;

    int lane = tid & 31, wid = tid >> 5;
    int wm = wid >> 2, wn = wid & 3;   // warp grid 2 x 4
    int g = lane >> 2, t4 = lane & 3;

    float acc[4][4][4];
    #pragma unroll
    for (int mi = 0; mi < 4; mi++)
        #pragma unroll
        for (int ni = 0; ni < 4; ni++)
            #pragma unroll
            for (int r = 0; r < 4; r++) acc[mi][ni][r] = 0.f;

    // async-load one 128x64 k-tile of A and B into stage st
    auto fill = [&](int k0, int st) {
        #pragma unroll
        for (int i = 0; i < 4; i++) {
            int o = tid + 256 * i;         // 0..1023
            int row = o >> 3, seg = o & 7; // 8 segs of 8 halves = 64
            uint32_t doff = (uint32_t)(st * GH_STAGE + row * 72 + seg * 8) * 2u;
            cp16(smem_u32 + doff, &A[(size_t)(m0 + row) * CDIM + k0 + seg * 8]);
            cp16(smem_u32 + (uint32_t)GH_B_OFF * 2u + doff,
                 &W[(size_t)(n0 + row) * CDIM + k0 + seg * 8]);
        }
        asm volatile("cp.async.commit_group;\n");
    };

    fill(0, 0);
    for (int j = 0; j < 8; j++) {
        if (j + 1 < 8) {
            fill((j + 1) * 64, (j + 1) & 1);
            asm volatile("cp.async.wait_group 1;\n");
        } else {
            asm volatile("cp.async.wait_group 0;\n");
        }
        __syncthreads();
        const __half* As = hsm + (j & 1) * GH_STAGE;
        const __half* Bs = hsm + GH_B_OFF + (j & 1) * GH_STAGE;
        #pragma unroll
        for (int kk = 0; kk < 64; kk += 16) {
            uint32_t afr[4][4], bfr[4][2];
            #pragma unroll
            for (int mi = 0; mi < 4; mi++) {
                int row = wm * 64 + mi * 16 + g;
                afr[mi][0] = *reinterpret_cast<const uint32_t*>(&As[row * 72 + kk + t4 * 2]);
                afr[mi][1] = *reinterpret_cast<const uint32_t*>(&As[(row + 8) * 72 + kk + t4 * 2]);
                afr[mi][2] = *reinterpret_cast<const uint32_t*>(&As[row * 72 + kk + 8 + t4 * 2]);
                afr[mi][3] = *reinterpret_cast<const uint32_t*>(&As[(row + 8) * 72 + kk + 8 + t4 * 2]);
            }
            #pragma unroll
            for (int ni = 0; ni < 4; ni++) {
                int col = wn * 32 + ni * 8 + g;
                bfr[ni][0] = *reinterpret_cast<const uint32_t*>(&Bs[col * 72 + kk + t4 * 2]);
                bfr[ni][1] = *reinterpret_cast<const uint32_t*>(&Bs[col * 72 + kk + 8 + t4 * 2]);
            }
            #pragma unroll
            for (int mi = 0; mi < 4; mi++)
                #pragma unroll
                for (int ni = 0; ni < 4; ni++)
                    mma_f16(acc[mi][ni], afr[mi], bfr[ni]);
        }
        __syncthreads();
    }

    // epilogue
    #pragma unroll
    for (int mi = 0; mi < 4; mi++) {
        #pragma unroll
        for (int ni = 0; ni < 4; ni++) {
            int row = m0 + wm * 64 + mi * 16 + g;
            int col = n0 + wn * 32 + ni * 8 + t4 * 2;
            float b0 = bias[col], b1 = bias[col + 1];
            emit<MODE>(row,     col,     acc[mi][ni][0] + b0, outp);
            emit<MODE>(row,     col + 1, acc[mi][ni][1] + b1, outp);
            emit<MODE>(row + 8, col,     acc[mi][ni][2] + b0, outp);
            emit<MODE>(row + 8, col + 1, acc[mi][ni][3] + b1, outp);
        }
    }
}

// ================= attention: one CTA per (block, head) =================
// smem floats: biasadd 4160 | q 64*68 | k 72*68 | v 65*68 | comb 64*68
#define SM_Q_OFF    4160
#define SM_K_OFF    (SM_Q_OFF + 64 * 68)
#define SM_V_OFF    (SM_K_OFF + 72 * 68)
#define SM_CB_OFF   (SM_V_OFF + 65 * 68)
#define ATTN_SMEM_FLOATS (SM_CB_OFF + 64 * 68)
#define ATTN_SMEM_BYTES  (ATTN_SMEM_FLOATS * 4)   // ~88.7 KB -> 2 CTAs/SM

__global__ void __launch_bounds__(256, 2) attn_kernel() {
    extern __shared__ float sm[];
    float* ba_s = sm;
    float* q_s = sm + SM_Q_OFF;
    float* k_s = sm + SM_K_OFF;
    float* v_s = sm + SM_V_OFF;
    float* cb_s = sm + SM_CB_OFF;

    int bid = blockIdx.x;      // 0..1023
    int h   = blockIdx.y;      // 0..7
    int tid = threadIdx.x;

    for (int i = tid; i < 4160; i += 256)
        ba_s[i] = g_biasadd[(size_t)bid * 4160 + i];
    for (int i = tid; i < 7 * 68; i += 256) k_s[65 * 68 + i] = 0.f;

    for (int f = tid; f < 64 * 16; f += 256) {
        int row = f >> 4, c4 = (f & 15) * 4;
        *reinterpret_cast<float4*>(&q_s[row * 68 + c4]) =
            *reinterpret_cast<const float4*>(&g_q[(size_t)(bid * 64 + row) * CDIM + h * 64 + c4]);
    }
    for (int f = tid; f < 65 * 16; f += 256) {
        int row = f / 16, c4 = (f & 15) * 4;
        size_t src = (size_t)(bid * 65 + row) * CDIM + h * 64 + c4;
        *reinterpret_cast<float4*>(&k_s[row * 68 + c4]) =
            *reinterpret_cast<const float4*>(&g_k[src]);
        *reinterpret_cast<float4*>(&v_s[row * 68 + c4]) =
            *reinterpret_cast<const float4*>(&g_v[src]);
    }
    __syncthreads();

    int lane = tid & 31, warp = tid >> 5;
    int t8 = lane & 7, g2 = lane >> 3;
    int r0 = warp * 8 + g2 * 2;

    const float* lew_g = g_lew + ((size_t)bid * NH + h) * 4160;

    float acc0[9], acc1[9];
    #pragma unroll
    for (int j = 0; j < 9; j++) { acc0[j] = 0.f; acc1[j] = 0.f; }
    #pragma unroll 4
    for (int d4 = 0; d4 < 16; d4++) {
        float4 qa = *reinterpret_cast<const float4*>(&q_s[r0 * 68 + d4 * 4]);
        float4 qb = *reinterpret_cast<const float4*>(&q_s[(r0 + 1) * 68 + d4 * 4]);
        #pragma unroll
        for (int j = 0; j < 9; j++) {
            float4 kv = *reinterpret_cast<const float4*>(&k_s[(t8 + 8 * j) * 68 + d4 * 4]);
            acc0[j] = fmaf(qa.x, kv.x, acc0[j]);
            acc0[j] = fmaf(qa.y, kv.y, acc0[j]);
            acc0[j] = fmaf(qa.z, kv.z, acc0[j]);
            acc0[j] = fmaf(qa.w, kv.w, acc0[j]);
            acc1[j] = fmaf(qb.x, kv.x, acc1[j]);
            acc1[j] = fmaf(qb.y, kv.y, acc1[j]);
            acc1[j] = fmaf(qb.z, kv.z, acc1[j]);
            acc1[j] = fmaf(qb.w, kv.w, acc1[j]);
        }
    }

    #pragma unroll
    for (int rr = 0; rr < 2; rr++) {
        float* acc = rr ? acc1 : acc0;
        int row = r0 + rr;
        float mx = -1e30f;
        #pragma unroll
        for (int j = 0; j < 9; j++) {
            int col = t8 + 8 * j;
            if (col < 65) {
                float s = acc[j] * 0.125f + ba_s[row * 65 + col];
                acc[j] = s;
                mx = fmaxf(mx, s);
            } else {
                acc[j] = -3e30f;
            }
        }
        mx = fmaxf(mx, __shfl_xor_sync(0xffffffffu, mx, 1));
        mx = fmaxf(mx, __shfl_xor_sync(0xffffffffu, mx, 2));
        mx = fmaxf(mx, __shfl_xor_sync(0xffffffffu, mx, 4));
        float sum = 0.f;
        #pragma unroll
        for (int j = 0; j < 9; j++) {
            float p = __expf(acc[j] - mx);
            acc[j] = p;
            sum += p;
        }
        sum += __shfl_xor_sync(0xffffffffu, sum, 1);
        sum += __shfl_xor_sync(0xffffffffu, sum, 2);
        sum += __shfl_xor_sync(0xffffffffu, sum, 4);
        float inv = 1.f / sum;
        #pragma unroll
        for (int j = 0; j < 9; j++) {
            int col = t8 + 8 * j;
            if (col < 65) {
                int idx = row * 65 + col;
                cb_s[row * 68 + col] = acc[j] * inv + __ldg(&lew_g[idx]);
            }
        }
    }
    __syncwarp();

    float o0[8], o1[8];
    #pragma unroll
    for (int j = 0; j < 8; j++) { o0[j] = 0.f; o1[j] = 0.f; }
    for (int k = 0; k < 65; k++) {
        float cv0 = cb_s[r0 * 68 + k];
        float cv1 = cb_s[(r0 + 1) * 68 + k];
        float4 va = *reinterpret_cast<const float4*>(&v_s[k * 68 + t8 * 8]);
        float4 vb = *reinterpret_cast<const float4*>(&v_s[k * 68 + t8 * 8 + 4]);
        o0[0] = fmaf(cv0, va.x, o0[0]); o0[1] = fmaf(cv0, va.y, o0[1]);
        o0[2] = fmaf(cv0, va.z, o0[2]); o0[3] = fmaf(cv0, va.w, o0[3]);
        o0[4] = fmaf(cv0, vb.x, o0[4]); o0[5] = fmaf(cv0, vb.y, o0[5]);
        o0[6] = fmaf(cv0, vb.z, o0[6]); o0[7] = fmaf(cv0, vb.w, o0[7]);
        o1[0] = fmaf(cv1, va.x, o1[0]); o1[1] = fmaf(cv1, va.y, o1[1]);
        o1[2] = fmaf(cv1, va.z, o1[2]); o1[3] = fmaf(cv1, va.w, o1[3]);
        o1[4] = fmaf(cv1, vb.x, o1[4]); o1[5] = fmaf(cv1, vb.y, o1[5]);
        o1[6] = fmaf(cv1, vb.z, o1[6]); o1[7] = fmaf(cv1, vb.w, o1[7]);
    }
    // fp16-round attention output at write: it feeds only the proj GEMM
    __half2* dst0 = reinterpret_cast<__half2*>(g_atth + (size_t)(bid * 64 + r0) * CDIM + h * 64 + t8 * 8);
    dst0[0] = __floats2half2_rn(o0[0], o0[1]);
    dst0[1] = __floats2half2_rn(o0[2], o0[3]);
    dst0[2] = __floats2half2_rn(o0[4], o0[5]);
    dst0[3] = __floats2half2_rn(o0[6], o0[7]);
    __half2* dst1 = reinterpret_cast<__half2*>(g_atth + (size_t)(bid * 64 + r0 + 1) * CDIM + h * 64 + t8 * 8);
    dst1[0] = __floats2half2_rn(o1[0], o1[1]);
    dst1[1] = __floats2half2_rn(o1[2], o1[3]);
    dst1[2] = __floats2half2_rn(o1[4], o1[5]);
    dst1[3] = __floats2half2_rn(o1[6], o1[7]);
}

// ================= host =================
extern "C" void kernel_launch(void* const* d_in, const int* in_sizes, int n_in,
                              void* d_out, int out_size) {
    (void)in_sizes; (void)n_in; (void)out_size;
    const float* x      = (const float*)d_in[0];
    const int*   amask  = (const int*)d_in[1];
    const float* edge   = (const float*)d_in[2];
    const float* qkv_w  = (const float*)d_in[3];
    const float* qkv_b  = (const float*)d_in[4];
    const float* proj_w = (const float*)d_in[5];
    const float* proj_b = (const float*)d_in[6];
    const float* eg_w   = (const float*)d_in[7];
    const float* eg_b   = (const float*)d_in[8];
    float* out = (float*)d_out;

    cudaFuncSetAttribute(attn_kernel, cudaFuncAttributeMaxDynamicSharedMemorySize, ATTN_SMEM_BYTES);
    cudaFuncSetAttribute(gemm_h<0>, cudaFuncAttributeMaxDynamicSharedMemorySize, GEMM_SMEM_BYTES);
    cudaFuncSetAttribute(gemm_h<1>, cudaFuncAttributeMaxDynamicSharedMemorySize, GEMM_SMEM_BYTES);
    cudaFuncSetAttribute(gemm_h<2>, cudaFuncAttributeMaxDynamicSharedMemorySize, GEMM_SMEM_BYTES);

    __half* d_xh;  cudaGetSymbolAddress((void**)&d_xh,  g_xh);
    __half* d_wqh; cudaGetSymbolAddress((void**)&d_wqh, g_wqh);
    __half* d_wph; cudaGetSymbolAddress((void**)&d_wph, g_wph);

    // pre-round GEMM inputs to fp16
    conv_h<<<(MX * CDIM / 4 + 255) / 256, 256>>>((const float4*)x, (__half2*)d_xh, MX * CDIM / 4);
    conv_h<<<(3 * CDIM * CDIM / 4 + 255) / 256, 256>>>((const float4*)qkv_w, (__half2*)d_wqh, 3 * CDIM * CDIM / 4);
    conv_h<<<(CDIM * CDIM / 4 + 255) / 256, 256>>>((const float4*)proj_w, (__half2*)d_wph, CDIM * CDIM / 4);

    mean_kernel<<<BNB, 256>>>(x);
    prep_kernel<<<BNB, 256>>>(edge, amask, eg_w, eg_b);

    // QKV: M=65536, N=1536
    gemm_h<0><<<dim3(1536 / 128, MX / 128), 256, GEMM_SMEM_BYTES>>>(d_xh, d_wqh, qkv_b, nullptr);
    // block-node K/V: M=1024 (blocks), N=1024 (k|v halves)
    gemm_h<1><<<dim3(1024 / 128, BNB / 128), 256, GEMM_SMEM_BYTES>>>(nullptr, d_wqh + (size_t)CDIM * CDIM, qkv_b + CDIM, nullptr);
    attn_kernel<<<dim3(BNB, NH), 256, ATTN_SMEM_BYTES>>>();
    // proj: M=65536, N=512
    gemm_h<2><<<dim3(512 / 128, MX / 128), 256, GEMM_SMEM_BYTES>>>(nullptr, d_wph, proj_b, out);
}

// round 7
// speedup vs baseline: 1.5080x; 1.1475x over previous
#include <cuda_runtime.h>
#include <cuda_fp16.h>
#include <cstdint>

#define NB_B   2
#define NB     512
#define LQ     64
#define KEYN   65
#define NH     8
#define HD     64
#define CDIM   512
#define NTOK   32768
#define BNB    (NB_B*NB)        // 1024 blocks total
#define MX     (NB_B*NTOK)      // 65536 x-rows
#define KVROWS (BNB*KEYN)       // 66560 kv-rows

// -------- device scratch (static, allocation-guard safe) --------
__device__ float  g_biasadd[(size_t)BNB*4160];
__device__ float  g_lew[(size_t)BNB*NH*4160];
__device__ __half g_xh [(size_t)MX*CDIM];       // fp16 x
__device__ __half g_wqh[(size_t)3*CDIM*CDIM];   // fp16 qkv_w
__device__ __half g_wph[(size_t)CDIM*CDIM];     // fp16 proj_w
__device__ __half g_bmh[(size_t)BNB*CDIM];      // fp16 block means
__device__ __half g_qh [(size_t)MX*CDIM];       // fp16 q
__device__ __half g_kh [(size_t)KVROWS*CDIM];   // fp16 k
__device__ __half g_vh [(size_t)KVROWS*CDIM];   // fp16 v
__device__ __half g_atth[(size_t)MX*CDIM];      // fp16 attention output

// ================= fp32 -> fp16 conversion =================
__global__ void conv_h(const float4* __restrict__ src, __half2* __restrict__ dst, int n4) {
    int i = blockIdx.x * blockDim.x + threadIdx.x;
    if (i < n4) {
        float4 v = src[i];
        dst[2 * i]     = __floats2half2_rn(v.x, v.y);
        dst[2 * i + 1] = __floats2half2_rn(v.z, v.w);
    }
}

// ================= block mean (fp16 output; feeds gemm only) =================
__global__ void mean_kernel(const float* __restrict__ x) {
    int blk = blockIdx.x;
    const float* base = x + (size_t)blk * (LQ * CDIM);
    for (int c = threadIdx.x; c < CDIM; c += blockDim.x) {
        float s = 0.f;
        #pragma unroll 8
        for (int l = 0; l < LQ; l++) s += base[(size_t)l * CDIM + c];
        g_bmh[(size_t)blk * CDIM + c] = __float2half_rn(s * (1.f / 64.f));
    }
}

// ================= prep: fold mask into bias, precompute lew =================
__global__ void __launch_bounds__(256) prep_kernel(const float* __restrict__ edge,
                                                   const int* __restrict__ amask,
                                                   const float* __restrict__ eg_w,
                                                   const float* __restrict__ eg_b) {
    int bid = blockIdx.x;
    const float4* e4 = reinterpret_cast<const float4*>(edge) + (size_t)bid * 4160;
    const int* mk = amask + (size_t)bid * 4160;
    float w[NH][4], b[NH];
    #pragma unroll
    for (int h = 0; h < NH; h++) {
        w[h][0] = eg_w[h * 4 + 0]; w[h][1] = eg_w[h * 4 + 1];
        w[h][2] = eg_w[h * 4 + 2]; w[h][3] = eg_w[h * 4 + 3];
        b[h] = eg_b[h];
    }
    for (int i = threadIdx.x; i < 4160; i += 256) {
        int q = i / 65;
        int k = i - q * 65;
        float4 e = e4[i];
        if (k == 64 || k == q) e = make_float4(0.f, 0.f, 0.f, 1.f);
        bool m = (mk[i] != 0);
        g_biasadd[(size_t)bid * 4160 + i] = m ? e.w : -1e30f;
        #pragma unroll
        for (int h = 0; h < NH; h++) {
            float lv = e.x * w[h][0] + e.y * w[h][1] + e.z * w[h][2] + e.w * w[h][3] + b[h];
            g_lew[((size_t)bid * NH + h) * 4160 + i] = m ? lv : 0.f;
        }
    }
}

// ================= fp16 mma helper =================
__device__ __forceinline__ void mma_f16(float* c, const uint32_t* a, const uint32_t* b) {
    asm volatile(
        "mma.sync.aligned.m16n8k16.row.col.f32.f16.f16.f32 "
        "{%0,%1,%2,%3}, {%4,%5,%6,%7}, {%8,%9}, {%0,%1,%2,%3};\n"
        : "+f"(c[0]), "+f"(c[1]), "+f"(c[2]), "+f"(c[3])
        : "r"(a[0]), "r"(a[1]), "r"(a[2]), "r"(a[3]),
          "r"(b[0]), "r"(b[1]));
}

__device__ __forceinline__ void cp16(uint32_t smem_dst, const __half* gmem_src) {
    asm volatile("cp.async.cg.shared.global [%0], [%1], 16;\n"
                 :: "r"(smem_dst), "l"(gmem_src));
}

// epilogue scatter (column pairs)
template <int MODE>
__device__ __forceinline__ void emit2(int row, int col, float v0, float v1, float* outp) {
    if (MODE == 2) {
        float2 f = make_float2(v0, v1);
        *reinterpret_cast<float2*>(&outp[(size_t)row * CDIM + col]) = f;
    } else {
        __half2 hv = __floats2half2_rn(v0, v1);
        if (MODE == 0) {
            if (col < CDIM) {
                *reinterpret_cast<__half2*>(&g_qh[(size_t)row * CDIM + col]) = hv;
            } else {
                size_t kvr = (size_t)((row >> 6) * KEYN + (row & 63));
                if (col < 2 * CDIM)
                    *reinterpret_cast<__half2*>(&g_kh[kvr * CDIM + (col - CDIM)]) = hv;
                else
                    *reinterpret_cast<__half2*>(&g_vh[kvr * CDIM + (col - 2 * CDIM)]) = hv;
            }
        } else {
            size_t r = (size_t)row * KEYN + (KEYN - 1);
            if (col < CDIM) *reinterpret_cast<__half2*>(&g_kh[r * CDIM + col]) = hv;
            else            *reinterpret_cast<__half2*>(&g_vh[r * CDIM + (col - CDIM)]) = hv;
        }
    }
}

// ================= fp16 GEMM: C = A[M,512] * W[N,512]^T + bias =================
#define GH_STAGE  (128 * 72)
#define GH_B_OFF  (2 * GH_STAGE)
#define GEMM_SMEM_BYTES (4 * GH_STAGE * 2)

template <int MODE>
__global__ void __launch_bounds__(256, 2) gemm_h(const __half* __restrict__ Ain,
                                                 const __half* __restrict__ W,
                                                 const float* __restrict__ bias,
                                                 float* __restrict__ outp) {
    const __half* A = (MODE == 1) ? g_bmh : (MODE == 2 ? g_atth : Ain);
    extern __shared__ __align__(16) __half hsm[];
    uint32_t smem_u32 = (uint32_t)__cvta_generic_to_shared(hsm);

    int tid = threadIdx.x;
    int n0 = blockIdx.x * 128;
    int m0 = blockIdx.y * 128;

    int lane = tid & 31, wid = tid >> 5;
    int wm = wid >> 2, wn = wid & 3;
    int g = lane >> 2, t4 = lane & 3;

    float acc[4][4][4];
    #pragma unroll
    for (int mi = 0; mi < 4; mi++)
        #pragma unroll
        for (int ni = 0; ni < 4; ni++)
            #pragma unroll
            for (int r = 0; r < 4; r++) acc[mi][ni][r] = 0.f;

    auto fill = [&](int k0, int st) {
        #pragma unroll
        for (int i = 0; i < 4; i++) {
            int o = tid + 256 * i;
            int row = o >> 3, seg = o & 7;
            uint32_t doff = (uint32_t)(st * GH_STAGE + row * 72 + seg * 8) * 2u;
            cp16(smem_u32 + doff, &A[(size_t)(m0 + row) * CDIM + k0 + seg * 8]);
            cp16(smem_u32 + (uint32_t)GH_B_OFF * 2u + doff,
                 &W[(size_t)(n0 + row) * CDIM + k0 + seg * 8]);
        }
        asm volatile("cp.async.commit_group;\n");
    };

    fill(0, 0);
    for (int j = 0; j < 8; j++) {
        if (j + 1 < 8) {
            fill((j + 1) * 64, (j + 1) & 1);
            asm volatile("cp.async.wait_group 1;\n");
        } else {
            asm volatile("cp.async.wait_group 0;\n");
        }
        __syncthreads();
        const __half* As = hsm + (j & 1) * GH_STAGE;
        const __half* Bs = hsm + GH_B_OFF + (j & 1) * GH_STAGE;
        #pragma unroll
        for (int kk = 0; kk < 64; kk += 16) {
            uint32_t afr[4][4], bfr[4][2];
            #pragma unroll
            for (int mi = 0; mi < 4; mi++) {
                int row = wm * 64 + mi * 16 + g;
                afr[mi][0] = *reinterpret_cast<const uint32_t*>(&As[row * 72 + kk + t4 * 2]);
                afr[mi][1] = *reinterpret_cast<const uint32_t*>(&As[(row + 8) * 72 + kk + t4 * 2]);
                afr[mi][2] = *reinterpret_cast<const uint32_t*>(&As[row * 72 + kk + 8 + t4 * 2]);
                afr[mi][3] = *reinterpret_cast<const uint32_t*>(&As[(row + 8) * 72 + kk + 8 + t4 * 2]);
            }
            #pragma unroll
            for (int ni = 0; ni < 4; ni++) {
                int col = wn * 32 + ni * 8 + g;
                bfr[ni][0] = *reinterpret_cast<const uint32_t*>(&Bs[col * 72 + kk + t4 * 2]);
                bfr[ni][1] = *reinterpret_cast<const uint32_t*>(&Bs[col * 72 + kk + 8 + t4 * 2]);
            }
            #pragma unroll
            for (int mi = 0; mi < 4; mi++)
                #pragma unroll
                for (int ni = 0; ni < 4; ni++)
                    mma_f16(acc[mi][ni], afr[mi], bfr[ni]);
        }
        __syncthreads();
    }

    #pragma unroll
    for (int mi = 0; mi < 4; mi++) {
        #pragma unroll
        for (int ni = 0; ni < 4; ni++) {
            int row = m0 + wm * 64 + mi * 16 + g;
            int col = n0 + wn * 32 + ni * 8 + t4 * 2;
            float b0 = bias[col], b1 = bias[col + 1];
            emit2<MODE>(row,     col, acc[mi][ni][0] + b0, acc[mi][ni][1] + b1, outp);
            emit2<MODE>(row + 8, col, acc[mi][ni][2] + b0, acc[mi][ni][3] + b1, outp);
        }
    }
}

// ================= attention: tensor-core, one CTA per (block, head) ==========
// 128 threads (4 warps). smem bytes:
//   ba   fp32 4160        @0      (16640)
//   q    fp16 64x72       @16640  (9216)
//   k    fp16 80x72       @25856  (11520)  rows 65..79 zero
//   vT   fp16 64x88       @37376  (11264)  [d][key], keys 65..79 zero
//   p    fp16 64x88       @48640  (11264)
#define AT_SMEM_BYTES 59904

__global__ void __launch_bounds__(128, 3) attn_kernel() {
    extern __shared__ char smc[];
    float*  ba_s = reinterpret_cast<float*>(smc);
    __half* q_s  = reinterpret_cast<__half*>(smc + 16640);
    __half* k_s  = reinterpret_cast<__half*>(smc + 25856);
    __half* vT   = reinterpret_cast<__half*>(smc + 37376);
    __half* p_s  = reinterpret_cast<__half*>(smc + 48640);

    int bid = blockIdx.x;      // 0..1023
    int h   = blockIdx.y;      // 0..7
    int tid = threadIdx.x;

    for (int i = tid; i < 4160; i += 128)
        ba_s[i] = g_biasadd[(size_t)bid * 4160 + i];

    const __half2* qg = reinterpret_cast<const __half2*>(g_qh + (size_t)(bid * 64) * CDIM + h * 64);
    for (int i = tid; i < 64 * 32; i += 128) {
        int row = i >> 5, c = i & 31;
        *reinterpret_cast<__half2*>(&q_s[row * 72 + c * 2]) = qg[row * 256 + c];
    }
    const __half2* kg = reinterpret_cast<const __half2*>(g_kh + (size_t)(bid * 65) * CDIM + h * 64);
    for (int i = tid; i < 65 * 32; i += 128) {
        int row = i >> 5, c = i & 31;
        *reinterpret_cast<__half2*>(&k_s[row * 72 + c * 2]) = kg[row * 256 + c];
    }
    // zero pad k rows 65..79 (15 rows x 72 halves = 540 words)
    for (int i = tid; i < 540; i += 128)
        reinterpret_cast<uint32_t*>(k_s + 65 * 72)[i] = 0u;
    // zero vT keys 65..79 for all d
    for (int i = tid; i < 64 * 15; i += 128) {
        int d = i / 15, ky = 65 + (i % 15);
        vT[d * 88 + ky] = __float2half(0.f);
    }
    // transpose V into vT[d][key]
    const __half2* vg = reinterpret_cast<const __half2*>(g_vh + (size_t)(bid * 65) * CDIM + h * 64);
    for (int i = tid; i < 65 * 32; i += 128) {
        int key = i >> 5, c = i & 31;
        __half2 v = vg[key * 256 + c];
        vT[(c * 2) * 88 + key]     = __low2half(v);
        vT[(c * 2 + 1) * 88 + key] = __high2half(v);
    }
    __syncthreads();

    int lane = tid & 31, w = tid >> 5;
    int g = lane >> 2, t4 = lane & 3;
    int r0 = w * 16;

    // ---- scores: S[r0..r0+15][0..79] via mma, per warp ----
    float acc[10][4];
    #pragma unroll
    for (int nt = 0; nt < 10; nt++)
        #pragma unroll
        for (int r = 0; r < 4; r++) acc[nt][r] = 0.f;

    #pragma unroll
    for (int kst = 0; kst < 4; kst++) {
        uint32_t a[4];
        a[0] = *reinterpret_cast<const uint32_t*>(&q_s[(r0 + g) * 72 + kst * 16 + t4 * 2]);
        a[1] = *reinterpret_cast<const uint32_t*>(&q_s[(r0 + g + 8) * 72 + kst * 16 + t4 * 2]);
        a[2] = *reinterpret_cast<const uint32_t*>(&q_s[(r0 + g) * 72 + kst * 16 + 8 + t4 * 2]);
        a[3] = *reinterpret_cast<const uint32_t*>(&q_s[(r0 + g + 8) * 72 + kst * 16 + 8 + t4 * 2]);
        #pragma unroll
        for (int nt = 0; nt < 10; nt++) {
            uint32_t b[2];
            b[0] = *reinterpret_cast<const uint32_t*>(&k_s[(nt * 8 + g) * 72 + kst * 16 + t4 * 2]);
            b[1] = *reinterpret_cast<const uint32_t*>(&k_s[(nt * 8 + g) * 72 + kst * 16 + 8 + t4 * 2]);
            mma_f16(acc[nt], a, b);
        }
    }

    // ---- softmax + lew on fragments ----
    const float* lewp = g_lew + ((size_t)bid * NH + h) * 4160;
    #pragma unroll
    for (int rr = 0; rr < 2; rr++) {
        int row = r0 + g + rr * 8;
        float v[20];
        float mx = -1e30f;
        #pragma unroll
        for (int nt = 0; nt < 10; nt++) {
            #pragma unroll
            for (int e = 0; e < 2; e++) {
                int col = nt * 8 + t4 * 2 + e;
                float s = (col < 65) ? fmaf(acc[nt][rr * 2 + e], 0.125f, ba_s[row * 65 + col])
                                     : -1e30f;
                v[nt * 2 + e] = s;
                mx = fmaxf(mx, s);
            }
        }
        mx = fmaxf(mx, __shfl_xor_sync(0xffffffffu, mx, 1));
        mx = fmaxf(mx, __shfl_xor_sync(0xffffffffu, mx, 2));
        float sum = 0.f;
        #pragma unroll
        for (int i = 0; i < 20; i++) {
            float p = __expf(v[i] - mx);
            v[i] = p;
            sum += p;
        }
        sum += __shfl_xor_sync(0xffffffffu, sum, 1);
        sum += __shfl_xor_sync(0xffffffffu, sum, 2);
        float inv = 1.f / sum;
        #pragma unroll
        for (int nt = 0; nt < 10; nt++) {
            int col = nt * 8 + t4 * 2;
            float c0 = (col < 65)     ? fmaf(v[nt * 2],     inv, __ldg(&lewp[row * 65 + col]))     : 0.f;
            float c1 = (col + 1 < 65) ? fmaf(v[nt * 2 + 1], inv, __ldg(&lewp[row * 65 + col + 1])) : 0.f;
            *reinterpret_cast<__half2*>(&p_s[row * 88 + col]) = __floats2half2_rn(c0, c1);
        }
    }
    __syncthreads();

    // ---- AV: O[r0..r0+15][0..63] = P[.,0..79] x V[0..79,.] ----
    float oc[8][4];
    #pragma unroll
    for (int nt = 0; nt < 8; nt++)
        #pragma unroll
        for (int r = 0; r < 4; r++) oc[nt][r] = 0.f;

    #pragma unroll
    for (int kst = 0; kst < 5; kst++) {
        uint32_t a[4];
        a[0] = *reinterpret_cast<const uint32_t*>(&p_s[(r0 + g) * 88 + kst * 16 + t4 * 2]);
        a[1] = *reinterpret_cast<const uint32_t*>(&p_s[(r0 + g + 8) * 88 + kst * 16 + t4 * 2]);
        a[2] = *reinterpret_cast<const uint32_t*>(&p_s[(r0 + g) * 88 + kst * 16 + 8 + t4 * 2]);
        a[3] = *reinterpret_cast<const uint32_t*>(&p_s[(r0 + g + 8) * 88 + kst * 16 + 8 + t4 * 2]);
        #pragma unroll
        for (int nt = 0; nt < 8; nt++) {
            uint32_t b[2];
            b[0] = *reinterpret_cast<const uint32_t*>(&vT[(nt * 8 + g) * 88 + kst * 16 + t4 * 2]);
            b[1] = *reinterpret_cast<const uint32_t*>(&vT[(nt * 8 + g) * 88 + kst * 16 + 8 + t4 * 2]);
            mma_f16(oc[nt], a, b);
        }
    }

    __half* og = g_atth + (size_t)(bid * 64) * CDIM + h * 64;
    #pragma unroll
    for (int nt = 0; nt < 8; nt++) {
        int col = nt * 8 + t4 * 2;
        *reinterpret_cast<__half2*>(&og[(size_t)(r0 + g) * CDIM + col]) =
            __floats2half2_rn(oc[nt][0], oc[nt][1]);
        *reinterpret_cast<__half2*>(&og[(size_t)(r0 + g + 8) * CDIM + col]) =
            __floats2half2_rn(oc[nt][2], oc[nt][3]);
    }
}

// ================= host =================
extern "C" void kernel_launch(void* const* d_in, const int* in_sizes, int n_in,
                              void* d_out, int out_size) {
    (void)in_sizes; (void)n_in; (void)out_size;
    const float* x      = (const float*)d_in[0];
    const int*   amask  = (const int*)d_in[1];
    const float* edge   = (const float*)d_in[2];
    const float* qkv_w  = (const float*)d_in[3];
    const float* qkv_b  = (const float*)d_in[4];
    const float* proj_w = (const float*)d_in[5];
    const float* proj_b = (const float*)d_in[6];
    const float* eg_w   = (const float*)d_in[7];
    const float* eg_b   = (const float*)d_in[8];
    float* out = (float*)d_out;

    cudaFuncSetAttribute(attn_kernel, cudaFuncAttributeMaxDynamicSharedMemorySize, AT_SMEM_BYTES);
    cudaFuncSetAttribute(gemm_h<0>, cudaFuncAttributeMaxDynamicSharedMemorySize, GEMM_SMEM_BYTES);
    cudaFuncSetAttribute(gemm_h<1>, cudaFuncAttributeMaxDynamicSharedMemorySize, GEMM_SMEM_BYTES);
    cudaFuncSetAttribute(gemm_h<2>, cudaFuncAttributeMaxDynamicSharedMemorySize, GEMM_SMEM_BYTES);

    __half* d_xh;  cudaGetSymbolAddress((void**)&d_xh,  g_xh);
    __half* d_wqh; cudaGetSymbolAddress((void**)&d_wqh, g_wqh);
    __half* d_wph; cudaGetSymbolAddress((void**)&d_wph, g_wph);

    conv_h<<<(MX * CDIM / 4 + 255) / 256, 256>>>((const float4*)x, (__half2*)d_xh, MX * CDIM / 4);
    conv_h<<<(3 * CDIM * CDIM / 4 + 255) / 256, 256>>>((const float4*)qkv_w, (__half2*)d_wqh, 3 * CDIM * CDIM / 4);
    conv_h<<<(CDIM * CDIM / 4 + 255) / 256, 256>>>((const float4*)proj_w, (__half2*)d_wph, CDIM * CDIM / 4);

    mean_kernel<<<BNB, 256>>>(x);
    prep_kernel<<<BNB, 256>>>(edge, amask, eg_w, eg_b);

    gemm_h<0><<<dim3(1536 / 128, MX / 128), 256, GEMM_SMEM_BYTES>>>(d_xh, d_wqh, qkv_b, nullptr);
    gemm_h<1><<<dim3(1024 / 128, BNB / 128), 256, GEMM_SMEM_BYTES>>>(nullptr, d_wqh + (size_t)CDIM * CDIM, qkv_b + CDIM, nullptr);
    attn_kernel<<<dim3(BNB, NH), 128, AT_SMEM_BYTES>>>();
    gemm_h<2><<<dim3(512 / 128, MX / 128), 256, GEMM_SMEM_BYTES>>>(nullptr, d_wph, proj_b, out);
}

// round 8
// speedup vs baseline: 1.6937x; 1.1231x over previous
#include <cuda_runtime.h>
#include <cuda_fp16.h>
#include <cstdint>

#define NB_B   2
#define NB     512
#define LQ     64
#define KEYN   65
#define NH     8
#define HD     64
#define CDIM   512
#define NTOK   32768
#define BNB    (NB_B*NB)        // 1024 blocks total
#define MX     (NB_B*NTOK)      // 65536 x-rows
#define KVROWS (BNB*KEYN)       // 66560 kv-rows

// -------- device scratch (static, allocation-guard safe) --------
__device__ __half g_biasadd[(size_t)BNB*4160];   // fp16 pre-masked additive bias
__device__ __half g_lewh[(size_t)BNB*NH*4160];   // fp16 lew
__device__ __half g_xh [(size_t)MX*CDIM];        // fp16 x
__device__ __half g_wqh[(size_t)3*CDIM*CDIM];    // fp16 qkv_w
__device__ __half g_wph[(size_t)CDIM*CDIM];      // fp16 proj_w
__device__ __half g_bmh[(size_t)BNB*CDIM];       // fp16 block means
__device__ __half g_qh [(size_t)MX*CDIM];        // fp16 q
__device__ __half g_kh [(size_t)KVROWS*CDIM];    // fp16 k
__device__ __half g_vh [(size_t)KVROWS*CDIM];    // fp16 v
__device__ __half g_atth[(size_t)MX*CDIM];       // fp16 attention output

// ================= fp32 -> fp16 conversion =================
__global__ void conv_h(const float4* __restrict__ src, __half2* __restrict__ dst, int n4) {
    int i = blockIdx.x * blockDim.x + threadIdx.x;
    if (i < n4) {
        float4 v = src[i];
        dst[2 * i]     = __floats2half2_rn(v.x, v.y);
        dst[2 * i + 1] = __floats2half2_rn(v.z, v.w);
    }
}

// ================= block mean (fp16 output; feeds gemm only) =================
__global__ void mean_kernel(const float* __restrict__ x) {
    int blk = blockIdx.x;
    const float* base = x + (size_t)blk * (LQ * CDIM);
    for (int c = threadIdx.x; c < CDIM; c += blockDim.x) {
        float s = 0.f;
        #pragma unroll 8
        for (int l = 0; l < LQ; l++) s += base[(size_t)l * CDIM + c];
        g_bmh[(size_t)blk * CDIM + c] = __float2half_rn(s * (1.f / 64.f));
    }
}

// ================= prep: fold mask into bias, precompute lew =================
__global__ void __launch_bounds__(256) prep_kernel(const float* __restrict__ edge,
                                                   const int* __restrict__ amask,
                                                   const float* __restrict__ eg_w,
                                                   const float* __restrict__ eg_b) {
    int bid = blockIdx.x;
    const float4* e4 = reinterpret_cast<const float4*>(edge) + (size_t)bid * 4160;
    const int* mk = amask + (size_t)bid * 4160;
    float w[NH][4], b[NH];
    #pragma unroll
    for (int h = 0; h < NH; h++) {
        w[h][0] = eg_w[h * 4 + 0]; w[h][1] = eg_w[h * 4 + 1];
        w[h][2] = eg_w[h * 4 + 2]; w[h][3] = eg_w[h * 4 + 3];
        b[h] = eg_b[h];
    }
    for (int i = threadIdx.x; i < 4160; i += 256) {
        int q = i / 65;
        int k = i - q * 65;
        float4 e = e4[i];
        if (k == 64 || k == q) e = make_float4(0.f, 0.f, 0.f, 1.f);
        bool m = (mk[i] != 0);
        g_biasadd[(size_t)bid * 4160 + i] = __float2half_rn(m ? e.w : -30000.f);
        #pragma unroll
        for (int h = 0; h < NH; h++) {
            float lv = e.x * w[h][0] + e.y * w[h][1] + e.z * w[h][2] + e.w * w[h][3] + b[h];
            g_lewh[((size_t)bid * NH + h) * 4160 + i] = __float2half_rn(m ? lv : 0.f);
        }
    }
}

// ================= mma / ldmatrix helpers =================
__device__ __forceinline__ void mma_f16(float* c, const uint32_t* a, const uint32_t* b) {
    asm volatile(
        "mma.sync.aligned.m16n8k16.row.col.f32.f16.f16.f32 "
        "{%0,%1,%2,%3}, {%4,%5,%6,%7}, {%8,%9}, {%0,%1,%2,%3};\n"
        : "+f"(c[0]), "+f"(c[1]), "+f"(c[2]), "+f"(c[3])
        : "r"(a[0]), "r"(a[1]), "r"(a[2]), "r"(a[3]),
          "r"(b[0]), "r"(b[1]));
}

__device__ __forceinline__ void ldsm4(uint32_t* r, uint32_t addr) {
    asm volatile("ldmatrix.sync.aligned.m8n8.x4.shared.b16 {%0,%1,%2,%3}, [%4];"
                 : "=r"(r[0]), "=r"(r[1]), "=r"(r[2]), "=r"(r[3]) : "r"(addr));
}

__device__ __forceinline__ void cp16(uint32_t smem_dst, const __half* gmem_src) {
    asm volatile("cp.async.cg.shared.global [%0], [%1], 16;\n"
                 :: "r"(smem_dst), "l"(gmem_src));
}

// epilogue scatter (column pairs)
template <int MODE>
__device__ __forceinline__ void emit2(int row, int col, float v0, float v1, float* outp) {
    if (MODE == 2) {
        float2 f = make_float2(v0, v1);
        *reinterpret_cast<float2*>(&outp[(size_t)row * CDIM + col]) = f;
    } else {
        __half2 hv = __floats2half2_rn(v0, v1);
        if (MODE == 0) {
            if (col < CDIM) {
                *reinterpret_cast<__half2*>(&g_qh[(size_t)row * CDIM + col]) = hv;
            } else {
                size_t kvr = (size_t)((row >> 6) * KEYN + (row & 63));
                if (col < 2 * CDIM)
                    *reinterpret_cast<__half2*>(&g_kh[kvr * CDIM + (col - CDIM)]) = hv;
                else
                    *reinterpret_cast<__half2*>(&g_vh[kvr * CDIM + (col - 2 * CDIM)]) = hv;
            }
        } else {
            size_t r = (size_t)row * KEYN + (KEYN - 1);
            if (col < CDIM) *reinterpret_cast<__half2*>(&g_kh[r * CDIM + col]) = hv;
            else            *reinterpret_cast<__half2*>(&g_vh[r * CDIM + (col - CDIM)]) = hv;
        }
    }
}

// ================= fp16 GEMM: C = A[M,512] * W[N,512]^T + bias =================
#define GH_STAGE  (128 * 72)
#define GH_B_OFF  (2 * GH_STAGE)
#define GEMM_SMEM_BYTES (4 * GH_STAGE * 2)

template <int MODE>
__global__ void __launch_bounds__(256, 2) gemm_h(const __half* __restrict__ Ain,
                                                 const __half* __restrict__ W,
                                                 const float* __restrict__ bias,
                                                 float* __restrict__ outp) {
    const __half* A = (MODE == 1) ? g_bmh : (MODE == 2 ? g_atth : Ain);
    extern __shared__ __align__(16) __half hsm[];
    uint32_t smem_u32 = (uint32_t)__cvta_generic_to_shared(hsm);

    int tid = threadIdx.x;
    int n0 = blockIdx.x * 128;
    int m0 = blockIdx.y * 128;

    int lane = tid & 31, wid = tid >> 5;
    int wm = wid >> 2, wn = wid & 3;
    int g = lane >> 2, t4 = lane & 3;

    // ldmatrix per-lane address terms (in halves)
    int a_term = (wm * 64 + (lane & 15)) * 72 + (lane >> 4) * 8;
    int b_term = (wn * 32 + (lane >> 4) * 8 + (lane & 7)) * 72 + ((lane >> 3) & 1) * 8;

    float acc[4][4][4];
    #pragma unroll
    for (int mi = 0; mi < 4; mi++)
        #pragma unroll
        for (int ni = 0; ni < 4; ni++)
            #pragma unroll
            for (int r = 0; r < 4; r++) acc[mi][ni][r] = 0.f;

    auto fill = [&](int k0, int st) {
        #pragma unroll
        for (int i = 0; i < 4; i++) {
            int o = tid + 256 * i;
            int row = o >> 3, seg = o & 7;
            uint32_t doff = (uint32_t)(st * GH_STAGE + row * 72 + seg * 8) * 2u;
            cp16(smem_u32 + doff, &A[(size_t)(m0 + row) * CDIM + k0 + seg * 8]);
            cp16(smem_u32 + (uint32_t)GH_B_OFF * 2u + doff,
                 &W[(size_t)(n0 + row) * CDIM + k0 + seg * 8]);
        }
        asm volatile("cp.async.commit_group;\n");
    };

    fill(0, 0);
    for (int j = 0; j < 8; j++) {
        if (j + 1 < 8) {
            fill((j + 1) * 64, (j + 1) & 1);
            asm volatile("cp.async.wait_group 1;\n");
        } else {
            asm volatile("cp.async.wait_group 0;\n");
        }
        __syncthreads();
        int st = (j & 1) * GH_STAGE;
        uint32_t a_base = smem_u32 + (uint32_t)(st + a_term) * 2u;
        uint32_t b_base = smem_u32 + (uint32_t)(GH_B_OFF + st + b_term) * 2u;
        #pragma unroll
        for (int kk = 0; kk < 64; kk += 16) {
            uint32_t afr[4][4], bfr[4][2];
            #pragma unroll
            for (int mi = 0; mi < 4; mi++)
                ldsm4(afr[mi], a_base + (uint32_t)(mi * 16 * 72 + kk) * 2u);
            #pragma unroll
            for (int jp = 0; jp < 2; jp++) {
                uint32_t bb[4];
                ldsm4(bb, b_base + (uint32_t)(jp * 16 * 72 + kk) * 2u);
                bfr[2 * jp][0] = bb[0]; bfr[2 * jp][1] = bb[1];
                bfr[2 * jp + 1][0] = bb[2]; bfr[2 * jp + 1][1] = bb[3];
            }
            #pragma unroll
            for (int mi = 0; mi < 4; mi++)
                #pragma unroll
                for (int ni = 0; ni < 4; ni++)
                    mma_f16(acc[mi][ni], afr[mi], bfr[ni]);
        }
        __syncthreads();
    }

    #pragma unroll
    for (int mi = 0; mi < 4; mi++) {
        #pragma unroll
        for (int ni = 0; ni < 4; ni++) {
            int row = m0 + wm * 64 + mi * 16 + g;
            int col = n0 + wn * 32 + ni * 8 + t4 * 2;
            float b0 = bias[col], b1 = bias[col + 1];
            emit2<MODE>(row,     col, acc[mi][ni][0] + b0, acc[mi][ni][1] + b1, outp);
            emit2<MODE>(row + 8, col, acc[mi][ni][2] + b0, acc[mi][ni][3] + b1, outp);
        }
    }
}

// ================= attention: tensor-core, one CTA per (block, head) ==========
// 128 threads (4 warps). smem bytes:
//   ba   fp16 4160        @0      (8320)
//   q    fp16 64x72       @8320   (9216)
//   k    fp16 80x72       @17536  (11520)  rows 65..79 zero
//   vT   fp16 64x88       @29056  (11264)  [d][key], keys 65..79 zero
//   p    fp16 64x88       @40320  (11264)
#define AT_SMEM_BYTES 51584

__global__ void __launch_bounds__(128, 4) attn_kernel() {
    extern __shared__ char smc[];
    __half* ba_s = reinterpret_cast<__half*>(smc);
    __half* q_s  = reinterpret_cast<__half*>(smc + 8320);
    __half* k_s  = reinterpret_cast<__half*>(smc + 17536);
    __half* vT   = reinterpret_cast<__half*>(smc + 29056);
    __half* p_s  = reinterpret_cast<__half*>(smc + 40320);

    int bid = blockIdx.x;      // 0..1023
    int h   = blockIdx.y;      // 0..7
    int tid = threadIdx.x;

    // ba copy as 32-bit words (4160 halves = 2080 words)
    {
        const uint32_t* src = reinterpret_cast<const uint32_t*>(g_biasadd + (size_t)bid * 4160);
        uint32_t* dst = reinterpret_cast<uint32_t*>(ba_s);
        for (int i = tid; i < 2080; i += 128) dst[i] = src[i];
    }

    const __half2* qg = reinterpret_cast<const __half2*>(g_qh + (size_t)(bid * 64) * CDIM + h * 64);
    for (int i = tid; i < 64 * 32; i += 128) {
        int row = i >> 5, c = i & 31;
        *reinterpret_cast<__half2*>(&q_s[row * 72 + c * 2]) = qg[row * 256 + c];
    }
    const __half2* kg = reinterpret_cast<const __half2*>(g_kh + (size_t)(bid * 65) * CDIM + h * 64);
    for (int i = tid; i < 65 * 32; i += 128) {
        int row = i >> 5, c = i & 31;
        *reinterpret_cast<__half2*>(&k_s[row * 72 + c * 2]) = kg[row * 256 + c];
    }
    for (int i = tid; i < 540; i += 128)
        reinterpret_cast<uint32_t*>(k_s + 65 * 72)[i] = 0u;
    for (int i = tid; i < 64 * 15; i += 128) {
        int d = i / 15, ky = 65 + (i % 15);
        vT[d * 88 + ky] = __float2half(0.f);
    }
    const __half2* vg = reinterpret_cast<const __half2*>(g_vh + (size_t)(bid * 65) * CDIM + h * 64);
    for (int i = tid; i < 65 * 32; i += 128) {
        int key = i >> 5, c = i & 31;
        __half2 v = vg[key * 256 + c];
        vT[(c * 2) * 88 + key]     = __low2half(v);
        vT[(c * 2 + 1) * 88 + key] = __high2half(v);
    }
    __syncthreads();

    int lane = tid & 31, w = tid >> 5;
    int g = lane >> 2, t4 = lane & 3;
    int r0 = w * 16;

    uint32_t q_u32 = (uint32_t)__cvta_generic_to_shared(q_s);
    uint32_t k_u32 = (uint32_t)__cvta_generic_to_shared(k_s);
    uint32_t v_u32 = (uint32_t)__cvta_generic_to_shared(vT);
    uint32_t p_u32 = (uint32_t)__cvta_generic_to_shared(p_s);

    // per-lane ldmatrix address terms
    uint32_t qa_base = q_u32 + (uint32_t)(((r0 + (lane & 15)) * 72 + (lane >> 4) * 8) * 2);
    uint32_t kb_term = (uint32_t)((((lane >> 4) * 8 + (lane & 7)) * 72 + ((lane >> 3) & 1) * 8) * 2);
    uint32_t pa_base = p_u32 + (uint32_t)(((r0 + (lane & 15)) * 88 + (lane >> 4) * 8) * 2);
    uint32_t vb_term = (uint32_t)((((lane >> 4) * 8 + (lane & 7)) * 88 + ((lane >> 3) & 1) * 8) * 2);

    // ---- scores: S[r0..r0+15][0..79] ----
    float acc[10][4];
    #pragma unroll
    for (int nt = 0; nt < 10; nt++)
        #pragma unroll
        for (int r = 0; r < 4; r++) acc[nt][r] = 0.f;

    #pragma unroll
    for (int kst = 0; kst < 4; kst++) {
        uint32_t a[4];
        ldsm4(a, qa_base + (uint32_t)(kst * 16 * 2));
        #pragma unroll
        for (int jp = 0; jp < 5; jp++) {
            uint32_t bb[4];
            ldsm4(bb, k_u32 + kb_term + (uint32_t)((jp * 16 * 72 + kst * 16) * 2));
            uint32_t b0[2] = {bb[0], bb[1]}, b1[2] = {bb[2], bb[3]};
            mma_f16(acc[2 * jp], a, b0);
            mma_f16(acc[2 * jp + 1], a, b1);
        }
    }

    // ---- softmax + lew on fragments ----
    const __half* lewp = g_lewh + ((size_t)bid * NH + h) * 4160;
    #pragma unroll
    for (int rr = 0; rr < 2; rr++) {
        int row = r0 + g + rr * 8;
        float v[20];
        float mx = -1e30f;
        #pragma unroll
        for (int nt = 0; nt < 10; nt++) {
            #pragma unroll
            for (int e = 0; e < 2; e++) {
                int col = nt * 8 + t4 * 2 + e;
                float s = (col < 65) ? fmaf(acc[nt][rr * 2 + e], 0.125f,
                                            __half2float(ba_s[row * 65 + col]))
                                     : -1e30f;
                v[nt * 2 + e] = s;
                mx = fmaxf(mx, s);
            }
        }
        mx = fmaxf(mx, __shfl_xor_sync(0xffffffffu, mx, 1));
        mx = fmaxf(mx, __shfl_xor_sync(0xffffffffu, mx, 2));
        float sum = 0.f;
        #pragma unroll
        for (int i = 0; i < 20; i++) {
            float p = __expf(v[i] - mx);
            v[i] = p;
            sum += p;
        }
        sum += __shfl_xor_sync(0xffffffffu, sum, 1);
        sum += __shfl_xor_sync(0xffffffffu, sum, 2);
        float inv = 1.f / sum;
        #pragma unroll
        for (int nt = 0; nt < 10; nt++) {
            int col = nt * 8 + t4 * 2;
            float c0 = (col < 65)     ? fmaf(v[nt * 2],     inv, __half2float(__ldg(&lewp[row * 65 + col])))     : 0.f;
            float c1 = (col + 1 < 65) ? fmaf(v[nt * 2 + 1], inv, __half2float(__ldg(&lewp[row * 65 + col + 1]))) : 0.f;
            *reinterpret_cast<__half2*>(&p_s[row * 88 + col]) = __floats2half2_rn(c0, c1);
        }
    }
    __syncthreads();

    // ---- AV: O[r0..r0+15][0..63] = P[.,0..79] x V[0..79,.] ----
    float oc[8][4];
    #pragma unroll
    for (int nt = 0; nt < 8; nt++)
        #pragma unroll
        for (int r = 0; r < 4; r++) oc[nt][r] = 0.f;

    #pragma unroll
    for (int kst = 0; kst < 5; kst++) {
        uint32_t a[4];
        ldsm4(a, pa_base + (uint32_t)(kst * 16 * 2));
        #pragma unroll
        for (int jp = 0; jp < 4; jp++) {
            uint32_t bb[4];
            ldsm4(bb, v_u32 + vb_term + (uint32_t)((jp * 16 * 88 + kst * 16) * 2));
            uint32_t b0[2] = {bb[0], bb[1]}, b1[2] = {bb[2], bb[3]};
            mma_f16(oc[2 * jp], a, b0);
            mma_f16(oc[2 * jp + 1], a, b1);
        }
    }

    __half* og = g_atth + (size_t)(bid * 64) * CDIM + h * 64;
    #pragma unroll
    for (int nt = 0; nt < 8; nt++) {
        int col = nt * 8 + t4 * 2;
        *reinterpret_cast<__half2*>(&og[(size_t)(r0 + g) * CDIM + col]) =
            __floats2half2_rn(oc[nt][0], oc[nt][1]);
        *reinterpret_cast<__half2*>(&og[(size_t)(r0 + g + 8) * CDIM + col]) =
            __floats2half2_rn(oc[nt][2], oc[nt][3]);
    }
}

// ================= host =================
extern "C" void kernel_launch(void* const* d_in, const int* in_sizes, int n_in,
                              void* d_out, int out_size) {
    (void)in_sizes; (void)n_in; (void)out_size;
    const float* x      = (const float*)d_in[0];
    const int*   amask  = (const int*)d_in[1];
    const float* edge   = (const float*)d_in[2];
    const float* qkv_w  = (const float*)d_in[3];
    const float* qkv_b  = (const float*)d_in[4];
    const float* proj_w = (const float*)d_in[5];
    const float* proj_b = (const float*)d_in[6];
    const float* eg_w   = (const float*)d_in[7];
    const float* eg_b   = (const float*)d_in[8];
    float* out = (float*)d_out;

    cudaFuncSetAttribute(attn_kernel, cudaFuncAttributeMaxDynamicSharedMemorySize, AT_SMEM_BYTES);
    cudaFuncSetAttribute(gemm_h<0>, cudaFuncAttributeMaxDynamicSharedMemorySize, GEMM_SMEM_BYTES);
    cudaFuncSetAttribute(gemm_h<1>, cudaFuncAttributeMaxDynamicSharedMemorySize, GEMM_SMEM_BYTES);
    cudaFuncSetAttribute(gemm_h<2>, cudaFuncAttributeMaxDynamicSharedMemorySize, GEMM_SMEM_BYTES);

    __half* d_xh;  cudaGetSymbolAddress((void**)&d_xh,  g_xh);
    __half* d_wqh; cudaGetSymbolAddress((void**)&d_wqh, g_wqh);
    __half* d_wph; cudaGetSymbolAddress((void**)&d_wph, g_wph);

    conv_h<<<(MX * CDIM / 4 + 255) / 256, 256>>>((const float4*)x, (__half2*)d_xh, MX * CDIM / 4);
    conv_h<<<(3 * CDIM * CDIM / 4 + 255) / 256, 256>>>((const float4*)qkv_w, (__half2*)d_wqh, 3 * CDIM * CDIM / 4);
    conv_h<<<(CDIM * CDIM / 4 + 255) / 256, 256>>>((const float4*)proj_w, (__half2*)d_wph, CDIM * CDIM / 4);

    mean_kernel<<<BNB, 256>>>(x);
    prep_kernel<<<BNB, 256>>>(edge, amask, eg_w, eg_b);

    gemm_h<0><<<dim3(1536 / 128, MX / 128), 256, GEMM_SMEM_BYTES>>>(d_xh, d_wqh, qkv_b, nullptr);
    gemm_h<1><<<dim3(1024 / 128, BNB / 128), 256, GEMM_SMEM_BYTES>>>(nullptr, d_wqh + (size_t)CDIM * CDIM, qkv_b + CDIM, nullptr);
    attn_kernel<<<dim3(BNB, NH), 128, AT_SMEM_BYTES>>>();
    gemm_h<2><<<dim3(512 / 128, MX / 128), 256, GEMM_SMEM_BYTES>>>(nullptr, d_wph, proj_b, out);
}

// round 9
// speedup vs baseline: 1.7071x; 1.0079x over previous
#include <cuda_runtime.h>
#include <cuda_fp16.h>
#include <cstdint>

#define NB_B   2
#define NB     512
#define LQ     64
#define KEYN   65
#define NH     8
#define HD     64
#define CDIM   512
#define NTOK   32768
#define BNB    (NB_B*NB)        // 1024 blocks total
#define MX     (NB_B*NTOK)      // 65536 x-rows
#define KVROWS (BNB*KEYN)       // 66560 kv-rows

// -------- device scratch (static, allocation-guard safe) --------
__device__ __half g_biasadd[(size_t)BNB*4160];   // fp16 pre-masked additive bias
__device__ __half g_lewh[(size_t)BNB*NH*4160];   // fp16 lew
__device__ __half g_xh [(size_t)MX*CDIM];        // fp16 x
__device__ __half g_wqh[(size_t)3*CDIM*CDIM];    // fp16 qkv_w
__device__ __half g_wph[(size_t)CDIM*CDIM];      // fp16 proj_w
__device__ __half g_bmh[(size_t)BNB*CDIM];       // fp16 block means
__device__ __half g_qh [(size_t)MX*CDIM];        // fp16 q
__device__ __half g_kh [(size_t)KVROWS*CDIM];    // fp16 k
__device__ __half g_vh [(size_t)KVROWS*CDIM];    // fp16 v
__device__ __half g_atth[(size_t)MX*CDIM];       // fp16 attention output

// ================= fp32 -> fp16 conversion (weights only) =================
__global__ void conv_h(const float4* __restrict__ src, __half2* __restrict__ dst, int n4) {
    int i = blockIdx.x * blockDim.x + threadIdx.x;
    if (i < n4) {
        float4 v = src[i];
        dst[2 * i]     = __floats2half2_rn(v.x, v.y);
        dst[2 * i + 1] = __floats2half2_rn(v.z, v.w);
    }
}

// ======== block mean + x->fp16 in one pass over x ========
__global__ void mean_conv_kernel(const float* __restrict__ x) {
    int blk = blockIdx.x;
    const float* base = x + (size_t)blk * (LQ * CDIM);
    __half* xout = g_xh + (size_t)blk * (LQ * CDIM);
    for (int c = threadIdx.x; c < CDIM; c += blockDim.x) {
        float s = 0.f;
        #pragma unroll 8
        for (int l = 0; l < LQ; l++) {
            float v = base[(size_t)l * CDIM + c];
            s += v;
            xout[(size_t)l * CDIM + c] = __float2half_rn(v);
        }
        g_bmh[(size_t)blk * CDIM + c] = __float2half_rn(s * (1.f / 64.f));
    }
}

// ================= prep: fold mask into bias, precompute lew =================
__global__ void __launch_bounds__(256) prep_kernel(const float* __restrict__ edge,
                                                   const int* __restrict__ amask,
                                                   const float* __restrict__ eg_w,
                                                   const float* __restrict__ eg_b) {
    int bid = blockIdx.x;
    const float4* e4 = reinterpret_cast<const float4*>(edge) + (size_t)bid * 4160;
    const int* mk = amask + (size_t)bid * 4160;
    float w[NH][4], b[NH];
    #pragma unroll
    for (int h = 0; h < NH; h++) {
        w[h][0] = eg_w[h * 4 + 0]; w[h][1] = eg_w[h * 4 + 1];
        w[h][2] = eg_w[h * 4 + 2]; w[h][3] = eg_w[h * 4 + 3];
        b[h] = eg_b[h];
    }
    for (int i = threadIdx.x; i < 4160; i += 256) {
        int q = i / 65;
        int k = i - q * 65;
        float4 e = e4[i];
        if (k == 64 || k == q) e = make_float4(0.f, 0.f, 0.f, 1.f);
        bool m = (mk[i] != 0);
        g_biasadd[(size_t)bid * 4160 + i] = __float2half_rn(m ? e.w : -30000.f);
        #pragma unroll
        for (int h = 0; h < NH; h++) {
            float lv = e.x * w[h][0] + e.y * w[h][1] + e.z * w[h][2] + e.w * w[h][3] + b[h];
            g_lewh[((size_t)bid * NH + h) * 4160 + i] = __float2half_rn(m ? lv : 0.f);
        }
    }
}

// ================= mma / ldmatrix helpers =================
__device__ __forceinline__ void mma_f16(float* c, const uint32_t* a, const uint32_t* b) {
    asm volatile(
        "mma.sync.aligned.m16n8k16.row.col.f32.f16.f16.f32 "
        "{%0,%1,%2,%3}, {%4,%5,%6,%7}, {%8,%9}, {%0,%1,%2,%3};\n"
        : "+f"(c[0]), "+f"(c[1]), "+f"(c[2]), "+f"(c[3])
        : "r"(a[0]), "r"(a[1]), "r"(a[2]), "r"(a[3]),
          "r"(b[0]), "r"(b[1]));
}

__device__ __forceinline__ void ldsm4(uint32_t* r, uint32_t addr) {
    asm volatile("ldmatrix.sync.aligned.m8n8.x4.shared.b16 {%0,%1,%2,%3}, [%4];"
                 : "=r"(r[0]), "=r"(r[1]), "=r"(r[2]), "=r"(r[3]) : "r"(addr));
}

__device__ __forceinline__ void cp16(uint32_t smem_dst, const __half* gmem_src) {
    asm volatile("cp.async.cg.shared.global [%0], [%1], 16;\n"
                 :: "r"(smem_dst), "l"(gmem_src));
}

// epilogue scatter (column pairs)
template <int MODE>
__device__ __forceinline__ void emit2(int row, int col, float v0, float v1, float* outp) {
    if (MODE == 2) {
        float2 f = make_float2(v0, v1);
        *reinterpret_cast<float2*>(&outp[(size_t)row * CDIM + col]) = f;
    } else {
        __half2 hv = __floats2half2_rn(v0, v1);
        if (MODE == 0) {
            if (col < CDIM) {
                *reinterpret_cast<__half2*>(&g_qh[(size_t)row * CDIM + col]) = hv;
            } else {
                size_t kvr = (size_t)((row >> 6) * KEYN + (row & 63));
                if (col < 2 * CDIM)
                    *reinterpret_cast<__half2*>(&g_kh[kvr * CDIM + (col - CDIM)]) = hv;
                else
                    *reinterpret_cast<__half2*>(&g_vh[kvr * CDIM + (col - 2 * CDIM)]) = hv;
            }
        } else {
            size_t r = (size_t)row * KEYN + (KEYN - 1);
            if (col < CDIM) *reinterpret_cast<__half2*>(&g_kh[r * CDIM + col]) = hv;
            else            *reinterpret_cast<__half2*>(&g_vh[r * CDIM + (col - CDIM)]) = hv;
        }
    }
}

// ================= fp16 GEMM: C = A[M,512] * W[N,512]^T + bias =================
// CTA tile 128x128, 128 threads = 4 warps (2x2), warp tile 64x64.
// k-tile 64 halves, 2-stage cp.async double buffer, 2 CTAs/SM.
#define GH_STAGE  (128 * 72)
#define GH_B_OFF  (2 * GH_STAGE)
#define GEMM_SMEM_BYTES (4 * GH_STAGE * 2)

template <int MODE>
__global__ void __launch_bounds__(128, 2) gemm_h(const __half* __restrict__ Ain,
                                                 const __half* __restrict__ W,
                                                 const float* __restrict__ bias,
                                                 float* __restrict__ outp) {
    const __half* A = (MODE == 1) ? g_bmh : (MODE == 2 ? g_atth : Ain);
    extern __shared__ __align__(16) __half hsm[];
    uint32_t smem_u32 = (uint32_t)__cvta_generic_to_shared(hsm);

    int tid = threadIdx.x;
    int n0 = blockIdx.x * 128;
    int m0 = blockIdx.y * 128;

    int lane = tid & 31, wid = tid >> 5;
    int wm = wid >> 1, wn = wid & 1;
    int g = lane >> 2, t4 = lane & 3;

    // ldmatrix per-lane address terms (in halves)
    int a_term = (wm * 64 + (lane & 15)) * 72 + (lane >> 4) * 8;
    int b_term = (wn * 64 + (lane >> 4) * 8 + (lane & 7)) * 72 + ((lane >> 3) & 1) * 8;

    float acc[4][8][4];
    #pragma unroll
    for (int mi = 0; mi < 4; mi++)
        #pragma unroll
        for (int ni = 0; ni < 8; ni++)
            #pragma unroll
            for (int r = 0; r < 4; r++) acc[mi][ni][r] = 0.f;

    auto fill = [&](int k0, int st) {
        #pragma unroll
        for (int i = 0; i < 8; i++) {
            int o = tid + 128 * i;
            int row = o >> 3, seg = o & 7;
            uint32_t doff = (uint32_t)(st * GH_STAGE + row * 72 + seg * 8) * 2u;
            cp16(smem_u32 + doff, &A[(size_t)(m0 + row) * CDIM + k0 + seg * 8]);
            cp16(smem_u32 + (uint32_t)GH_B_OFF * 2u + doff,
                 &W[(size_t)(n0 + row) * CDIM + k0 + seg * 8]);
        }
        asm volatile("cp.async.commit_group;\n");
    };

    fill(0, 0);
    for (int j = 0; j < 8; j++) {
        if (j + 1 < 8) {
            fill((j + 1) * 64, (j + 1) & 1);
            asm volatile("cp.async.wait_group 1;\n");
        } else {
            asm volatile("cp.async.wait_group 0;\n");
        }
        __syncthreads();
        int st = (j & 1) * GH_STAGE;
        uint32_t a_base = smem_u32 + (uint32_t)(st + a_term) * 2u;
        uint32_t b_base = smem_u32 + (uint32_t)(GH_B_OFF + st + b_term) * 2u;
        #pragma unroll
        for (int kk = 0; kk < 64; kk += 16) {
            uint32_t afr[4][4], bfr[8][2];
            #pragma unroll
            for (int mi = 0; mi < 4; mi++)
                ldsm4(afr[mi], a_base + (uint32_t)(mi * 16 * 72 + kk) * 2u);
            #pragma unroll
            for (int jp = 0; jp < 4; jp++) {
                uint32_t bb[4];
                ldsm4(bb, b_base + (uint32_t)(jp * 16 * 72 + kk) * 2u);
                bfr[2 * jp][0] = bb[0]; bfr[2 * jp][1] = bb[1];
                bfr[2 * jp + 1][0] = bb[2]; bfr[2 * jp + 1][1] = bb[3];
            }
            #pragma unroll
            for (int mi = 0; mi < 4; mi++)
                #pragma unroll
                for (int ni = 0; ni < 8; ni++)
                    mma_f16(acc[mi][ni], afr[mi], bfr[ni]);
        }
        __syncthreads();
    }

    #pragma unroll
    for (int mi = 0; mi < 4; mi++) {
        #pragma unroll
        for (int ni = 0; ni < 8; ni++) {
            int row = m0 + wm * 64 + mi * 16 + g;
            int col = n0 + wn * 64 + ni * 8 + t4 * 2;
            float b0 = bias[col], b1 = bias[col + 1];
            emit2<MODE>(row,     col, acc[mi][ni][0] + b0, acc[mi][ni][1] + b1, outp);
            emit2<MODE>(row + 8, col, acc[mi][ni][2] + b0, acc[mi][ni][3] + b1, outp);
        }
    }
}

// ================= attention: tensor-core, one CTA per (block, head) ==========
// 128 threads (4 warps). smem bytes:
//   ba   fp16 4160        @0      (8320)
//   q    fp16 64x72       @8320   (9216)
//   k    fp16 80x72       @17536  (11520)  rows 65..79 zero
//   vT   fp16 64x88       @29056  (11264)  [d][key], keys 65..79 zero
//   p    fp16 64x88       @40320  (11264)
#define AT_SMEM_BYTES 51584

__global__ void __launch_bounds__(128, 4) attn_kernel() {
    extern __shared__ char smc[];
    __half* ba_s = reinterpret_cast<__half*>(smc);
    __half* q_s  = reinterpret_cast<__half*>(smc + 8320);
    __half* k_s  = reinterpret_cast<__half*>(smc + 17536);
    __half* vT   = reinterpret_cast<__half*>(smc + 29056);
    __half* p_s  = reinterpret_cast<__half*>(smc + 40320);

    int bid = blockIdx.x;      // 0..1023
    int h   = blockIdx.y;      // 0..7
    int tid = threadIdx.x;

    {
        const uint32_t* src = reinterpret_cast<const uint32_t*>(g_biasadd + (size_t)bid * 4160);
        uint32_t* dst = reinterpret_cast<uint32_t*>(ba_s);
        for (int i = tid; i < 2080; i += 128) dst[i] = src[i];
    }

    const __half2* qg = reinterpret_cast<const __half2*>(g_qh + (size_t)(bid * 64) * CDIM + h * 64);
    for (int i = tid; i < 64 * 32; i += 128) {
        int row = i >> 5, c = i & 31;
        *reinterpret_cast<__half2*>(&q_s[row * 72 + c * 2]) = qg[row * 256 + c];
    }
    const __half2* kg = reinterpret_cast<const __half2*>(g_kh + (size_t)(bid * 65) * CDIM + h * 64);
    for (int i = tid; i < 65 * 32; i += 128) {
        int row = i >> 5, c = i & 31;
        *reinterpret_cast<__half2*>(&k_s[row * 72 + c * 2]) = kg[row * 256 + c];
    }
    for (int i = tid; i < 540; i += 128)
        reinterpret_cast<uint32_t*>(k_s + 65 * 72)[i] = 0u;
    for (int i = tid; i < 64 * 15; i += 128) {
        int d = i / 15, ky = 65 + (i % 15);
        vT[d * 88 + ky] = __float2half(0.f);
    }
    const __half2* vg = reinterpret_cast<const __half2*>(g_vh + (size_t)(bid * 65) * CDIM + h * 64);
    for (int i = tid; i < 65 * 32; i += 128) {
        int key = i >> 5, c = i & 31;
        __half2 v = vg[key * 256 + c];
        vT[(c * 2) * 88 + key]     = __low2half(v);
        vT[(c * 2 + 1) * 88 + key] = __high2half(v);
    }
    __syncthreads();

    int lane = tid & 31, w = tid >> 5;
    int g = lane >> 2, t4 = lane & 3;
    int r0 = w * 16;

    uint32_t q_u32 = (uint32_t)__cvta_generic_to_shared(q_s);
    uint32_t k_u32 = (uint32_t)__cvta_generic_to_shared(k_s);
    uint32_t v_u32 = (uint32_t)__cvta_generic_to_shared(vT);
    uint32_t p_u32 = (uint32_t)__cvta_generic_to_shared(p_s);

    uint32_t qa_base = q_u32 + (uint32_t)(((r0 + (lane & 15)) * 72 + (lane >> 4) * 8) * 2);
    uint32_t kb_term = (uint32_t)((((lane >> 4) * 8 + (lane & 7)) * 72 + ((lane >> 3) & 1) * 8) * 2);
    uint32_t pa_base = p_u32 + (uint32_t)(((r0 + (lane & 15)) * 88 + (lane >> 4) * 8) * 2);
    uint32_t vb_term = (uint32_t)((((lane >> 4) * 8 + (lane & 7)) * 88 + ((lane >> 3) & 1) * 8) * 2);

    // ---- scores: S[r0..r0+15][0..79] ----
    float acc[10][4];
    #pragma unroll
    for (int nt = 0; nt < 10; nt++)
        #pragma unroll
        for (int r = 0; r < 4; r++) acc[nt][r] = 0.f;

    #pragma unroll
    for (int kst = 0; kst < 4; kst++) {
        uint32_t a[4];
        ldsm4(a, qa_base + (uint32_t)(kst * 16 * 2));
        #pragma unroll
        for (int jp = 0; jp < 5; jp++) {
            uint32_t bb[4];
            ldsm4(bb, k_u32 + kb_term + (uint32_t)((jp * 16 * 72 + kst * 16) * 2));
            uint32_t b0[2] = {bb[0], bb[1]}, b1[2] = {bb[2], bb[3]};
            mma_f16(acc[2 * jp], a, b0);
            mma_f16(acc[2 * jp + 1], a, b1);
        }
    }

    // ---- softmax + lew on fragments ----
    const __half* lewp = g_lewh + ((size_t)bid * NH + h) * 4160;
    #pragma unroll
    for (int rr = 0; rr < 2; rr++) {
        int row = r0 + g + rr * 8;
        float v[20];
        float mx = -1e30f;
        #pragma unroll
        for (int nt = 0; nt < 10; nt++) {
            #pragma unroll
            for (int e = 0; e < 2; e++) {
                int col = nt * 8 + t4 * 2 + e;
                float s = (col < 65) ? fmaf(acc[nt][rr * 2 + e], 0.125f,
                                            __half2float(ba_s[row * 65 + col]))
                                     : -1e30f;
                v[nt * 2 + e] = s;
                mx = fmaxf(mx, s);
            }
        }
        mx = fmaxf(mx, __shfl_xor_sync(0xffffffffu, mx, 1));
        mx = fmaxf(mx, __shfl_xor_sync(0xffffffffu, mx, 2));
        float sum = 0.f;
        #pragma unroll
        for (int i = 0; i < 20; i++) {
            float p = __expf(v[i] - mx);
            v[i] = p;
            sum += p;
        }
        sum += __shfl_xor_sync(0xffffffffu, sum, 1);
        sum += __shfl_xor_sync(0xffffffffu, sum, 2);
        float inv = 1.f / sum;
        #pragma unroll
        for (int nt = 0; nt < 10; nt++) {
            int col = nt * 8 + t4 * 2;
            float c0 = (col < 65)     ? fmaf(v[nt * 2],     inv, __half2float(__ldg(&lewp[row * 65 + col])))     : 0.f;
            float c1 = (col + 1 < 65) ? fmaf(v[nt * 2 + 1], inv, __half2float(__ldg(&lewp[row * 65 + col + 1]))) : 0.f;
            *reinterpret_cast<__half2*>(&p_s[row * 88 + col]) = __floats2half2_rn(c0, c1);
        }
    }
    __syncthreads();

    // ---- AV: O[r0..r0+15][0..63] = P[.,0..79] x V[0..79,.] ----
    float oc[8][4];
    #pragma unroll
    for (int nt = 0; nt < 8; nt++)
        #pragma unroll
        for (int r = 0; r < 4; r++) oc[nt][r] = 0.f;

    #pragma unroll
    for (int kst = 0; kst < 5; kst++) {
        uint32_t a[4];
        ldsm4(a, pa_base + (uint32_t)(kst * 16 * 2));
        #pragma unroll
        for (int jp = 0; jp < 4; jp++) {
            uint32_t bb[4];
            ldsm4(bb, v_u32 + vb_term + (uint32_t)((jp * 16 * 88 + kst * 16) * 2));
            uint32_t b0[2] = {bb[0], bb[1]}, b1[2] = {bb[2], bb[3]};
            mma_f16(oc[2 * jp], a, b0);
            mma_f16(oc[2 * jp + 1], a, b1);
        }
    }

    __half* og = g_atth + (size_t)(bid * 64) * CDIM + h * 64;
    #pragma unroll
    for (int nt = 0; nt < 8; nt++) {
        int col = nt * 8 + t4 * 2;
        *reinterpret_cast<__half2*>(&og[(size_t)(r0 + g) * CDIM + col]) =
            __floats2half2_rn(oc[nt][0], oc[nt][1]);
        *reinterpret_cast<__half2*>(&og[(size_t)(r0 + g + 8) * CDIM + col]) =
            __floats2half2_rn(oc[nt][2], oc[nt][3]);
    }
}

// ================= host =================
extern "C" void kernel_launch(void* const* d_in, const int* in_sizes, int n_in,
                              void* d_out, int out_size) {
    (void)in_sizes; (void)n_in; (void)out_size;
    const float* x      = (const float*)d_in[0];
    const int*   amask  = (const int*)d_in[1];
    const float* edge   = (const float*)d_in[2];
    const float* qkv_w  = (const float*)d_in[3];
    const float* qkv_b  = (const float*)d_in[4];
    const float* proj_w = (const float*)d_in[5];
    const float* proj_b = (const float*)d_in[6];
    const float* eg_w   = (const float*)d_in[7];
    const float* eg_b   = (const float*)d_in[8];
    float* out = (float*)d_out;

    cudaFuncSetAttribute(attn_kernel, cudaFuncAttributeMaxDynamicSharedMemorySize, AT_SMEM_BYTES);
    cudaFuncSetAttribute(gemm_h<0>, cudaFuncAttributeMaxDynamicSharedMemorySize, GEMM_SMEM_BYTES);
    cudaFuncSetAttribute(gemm_h<1>, cudaFuncAttributeMaxDynamicSharedMemorySize, GEMM_SMEM_BYTES);
    cudaFuncSetAttribute(gemm_h<2>, cudaFuncAttributeMaxDynamicSharedMemorySize, GEMM_SMEM_BYTES);

    __half* d_xh;  cudaGetSymbolAddress((void**)&d_xh,  g_xh);
    __half* d_wqh; cudaGetSymbolAddress((void**)&d_wqh, g_wqh);
    __half* d_wph; cudaGetSymbolAddress((void**)&d_wph, g_wph);

    conv_h<<<(3 * CDIM * CDIM / 4 + 255) / 256, 256>>>((const float4*)qkv_w, (__half2*)d_wqh, 3 * CDIM * CDIM / 4);
    conv_h<<<(CDIM * CDIM / 4 + 255) / 256, 256>>>((const float4*)proj_w, (__half2*)d_wph, CDIM * CDIM / 4);

    mean_conv_kernel<<<BNB, 256>>>(x);
    prep_kernel<<<BNB, 256>>>(edge, amask, eg_w, eg_b);

    gemm_h<0><<<dim3(1536 / 128, MX / 128), 128, GEMM_SMEM_BYTES>>>(d_xh, d_wqh, qkv_b, nullptr);
    gemm_h<1><<<dim3(1024 / 128, BNB / 128), 128, GEMM_SMEM_BYTES>>>(nullptr, d_wqh + (size_t)CDIM * CDIM, qkv_b + CDIM, nullptr);
    attn_kernel<<<dim3(BNB, NH), 128, AT_SMEM_BYTES>>>();
    gemm_h<2><<<dim3(512 / 128, MX / 128), 128, GEMM_SMEM_BYTES>>>(nullptr, d_wph, proj_b, out);
}

// round 10
// speedup vs baseline: 2.0191x; 1.1827x over previous
#include <cuda_runtime.h>
#include <cuda_fp16.h>
#include <cstdint>

#define NB_B   2
#define NB     512
#define LQ     64
#define KEYN   65
#define NH     8
#define HD     64
#define CDIM   512
#define NTOK   32768
#define BNB    (NB_B*NB)        // 1024 blocks total
#define MX     (NB_B*NTOK)      // 65536 x-rows
#define KVROWS (BNB*KEYN)       // 66560 kv-rows

// -------- device scratch (static, allocation-guard safe) --------
__device__ __half g_biasadd[(size_t)BNB*4160];   // fp16 pre-masked additive bias
__device__ __half g_lewh[(size_t)BNB*NH*4160];   // fp16 lew
__device__ __half g_xh [(size_t)MX*CDIM];        // fp16 x
__device__ __half g_wqh[(size_t)3*CDIM*CDIM];    // fp16 qkv_w
__device__ __half g_wph[(size_t)CDIM*CDIM];      // fp16 proj_w
__device__ __half g_bmh[(size_t)BNB*CDIM];       // fp16 block means
__device__ __half g_qh [(size_t)MX*CDIM];        // fp16 q
__device__ __half g_kh [(size_t)KVROWS*CDIM];    // fp16 k
__device__ __half g_vh [(size_t)KVROWS*CDIM];    // fp16 v
__device__ __half g_atth[(size_t)MX*CDIM];       // fp16 attention output

// ================= fp32 -> fp16 conversion (weights only) =================
__global__ void conv_h(const float4* __restrict__ src, __half2* __restrict__ dst, int n4) {
    int i = blockIdx.x * blockDim.x + threadIdx.x;
    if (i < n4) {
        float4 v = src[i];
        dst[2 * i]     = __floats2half2_rn(v.x, v.y);
        dst[2 * i + 1] = __floats2half2_rn(v.z, v.w);
    }
}

// ======== block mean + x->fp16 in one pass over x ========
__global__ void mean_conv_kernel(const float* __restrict__ x) {
    int blk = blockIdx.x;
    const float* base = x + (size_t)blk * (LQ * CDIM);
    __half* xout = g_xh + (size_t)blk * (LQ * CDIM);
    for (int c = threadIdx.x; c < CDIM; c += blockDim.x) {
        float s = 0.f;
        #pragma unroll 8
        for (int l = 0; l < LQ; l++) {
            float v = base[(size_t)l * CDIM + c];
            s += v;
            xout[(size_t)l * CDIM + c] = __float2half_rn(v);
        }
        g_bmh[(size_t)blk * CDIM + c] = __float2half_rn(s * (1.f / 64.f));
    }
}

// ================= prep: fold mask into bias, precompute lew =================
__global__ void __launch_bounds__(256) prep_kernel(const float* __restrict__ edge,
                                                   const int* __restrict__ amask,
                                                   const float* __restrict__ eg_w,
                                                   const float* __restrict__ eg_b) {
    int bid = blockIdx.x;
    int base = blockIdx.y * 2080;
    const float4* e4 = reinterpret_cast<const float4*>(edge) + (size_t)bid * 4160;
    const int* mk = amask + (size_t)bid * 4160;
    float w[NH][4], b[NH];
    #pragma unroll
    for (int h = 0; h < NH; h++) {
        w[h][0] = eg_w[h * 4 + 0]; w[h][1] = eg_w[h * 4 + 1];
        w[h][2] = eg_w[h * 4 + 2]; w[h][3] = eg_w[h * 4 + 3];
        b[h] = eg_b[h];
    }
    for (int i = base + threadIdx.x; i < base + 2080; i += 256) {
        int q = i / 65;
        int k = i - q * 65;
        float4 e = e4[i];
        if (k == 64 || k == q) e = make_float4(0.f, 0.f, 0.f, 1.f);
        bool m = (mk[i] != 0);
        g_biasadd[(size_t)bid * 4160 + i] = __float2half_rn(m ? e.w : -30000.f);
        #pragma unroll
        for (int h = 0; h < NH; h++) {
            float lv = e.x * w[h][0] + e.y * w[h][1] + e.z * w[h][2] + e.w * w[h][3] + b[h];
            g_lewh[((size_t)bid * NH + h) * 4160 + i] = __float2half_rn(m ? lv : 0.f);
        }
    }
}

// ================= mma / ldmatrix helpers =================
__device__ __forceinline__ void mma_f16(float* c, const uint32_t* a, const uint32_t* b) {
    asm volatile(
        "mma.sync.aligned.m16n8k16.row.col.f32.f16.f16.f32 "
        "{%0,%1,%2,%3}, {%4,%5,%6,%7}, {%8,%9}, {%0,%1,%2,%3};\n"
        : "+f"(c[0]), "+f"(c[1]), "+f"(c[2]), "+f"(c[3])
        : "r"(a[0]), "r"(a[1]), "r"(a[2]), "r"(a[3]),
          "r"(b[0]), "r"(b[1]));
}

__device__ __forceinline__ void ldsm4(uint32_t* r, uint32_t addr) {
    asm volatile("ldmatrix.sync.aligned.m8n8.x4.shared.b16 {%0,%1,%2,%3}, [%4];"
                 : "=r"(r[0]), "=r"(r[1]), "=r"(r[2]), "=r"(r[3]) : "r"(addr));
}

__device__ __forceinline__ void ldsm4t(uint32_t* r, uint32_t addr) {
    asm volatile("ldmatrix.sync.aligned.m8n8.x4.trans.shared.b16 {%0,%1,%2,%3}, [%4];"
                 : "=r"(r[0]), "=r"(r[1]), "=r"(r[2]), "=r"(r[3]) : "r"(addr));
}

__device__ __forceinline__ void cp16(uint32_t smem_dst, const __half* gmem_src) {
    asm volatile("cp.async.cg.shared.global [%0], [%1], 16;\n"
                 :: "r"(smem_dst), "l"(gmem_src));
}

// epilogue scatter (column pairs)
template <int MODE>
__device__ __forceinline__ void emit2(int row, int col, float v0, float v1, float* outp) {
    if (MODE == 2) {
        float2 f = make_float2(v0, v1);
        *reinterpret_cast<float2*>(&outp[(size_t)row * CDIM + col]) = f;
    } else {
        __half2 hv = __floats2half2_rn(v0, v1);
        if (MODE == 0) {
            if (col < CDIM) {
                *reinterpret_cast<__half2*>(&g_qh[(size_t)row * CDIM + col]) = hv;
            } else {
                size_t kvr = (size_t)((row >> 6) * KEYN + (row & 63));
                if (col < 2 * CDIM)
                    *reinterpret_cast<__half2*>(&g_kh[kvr * CDIM + (col - CDIM)]) = hv;
                else
                    *reinterpret_cast<__half2*>(&g_vh[kvr * CDIM + (col - 2 * CDIM)]) = hv;
            }
        } else {
            size_t r = (size_t)row * KEYN + (KEYN - 1);
            if (col < CDIM) *reinterpret_cast<__half2*>(&g_kh[r * CDIM + col]) = hv;
            else            *reinterpret_cast<__half2*>(&g_vh[r * CDIM + (col - CDIM)]) = hv;
        }
    }
}

// ================= fp16 GEMM: C = A[M,512] * W[N,512]^T + bias =================
// CTA tile 128x128, 128 threads = 4 warps (2x2), warp tile 64x64.
// k-tile 64 halves, 3-stage cp.async pipeline, 2 CTAs/SM.
#define GH_STAGE  (128 * 72)
#define GH_B_OFF  (3 * GH_STAGE)
#define GEMM_SMEM_BYTES (6 * GH_STAGE * 2)   // 110592 B

template <int MODE>
__global__ void __launch_bounds__(128, 2) gemm_h(const __half* __restrict__ Ain,
                                                 const __half* __restrict__ W,
                                                 const float* __restrict__ bias,
                                                 float* __restrict__ outp) {
    const __half* A = (MODE == 1) ? g_bmh : (MODE == 2 ? g_atth : Ain);
    extern __shared__ __align__(16) __half hsm[];
    uint32_t smem_u32 = (uint32_t)__cvta_generic_to_shared(hsm);

    int tid = threadIdx.x;
    int n0 = blockIdx.x * 128;
    int m0 = blockIdx.y * 128;

    int lane = tid & 31, wid = tid >> 5;
    int wm = wid >> 1, wn = wid & 1;
    int g = lane >> 2, t4 = lane & 3;

    int a_term = (wm * 64 + (lane & 15)) * 72 + (lane >> 4) * 8;
    int b_term = (wn * 64 + (lane >> 4) * 8 + (lane & 7)) * 72 + ((lane >> 3) & 1) * 8;

    float acc[4][8][4];
    #pragma unroll
    for (int mi = 0; mi < 4; mi++)
        #pragma unroll
        for (int ni = 0; ni < 8; ni++)
            #pragma unroll
            for (int r = 0; r < 4; r++) acc[mi][ni][r] = 0.f;

    auto fill = [&](int k0, int st) {
        #pragma unroll
        for (int i = 0; i < 8; i++) {
            int o = tid + 128 * i;
            int row = o >> 3, seg = o & 7;
            uint32_t doff = (uint32_t)(st * GH_STAGE + row * 72 + seg * 8) * 2u;
            cp16(smem_u32 + doff, &A[(size_t)(m0 + row) * CDIM + k0 + seg * 8]);
            cp16(smem_u32 + (uint32_t)GH_B_OFF * 2u + doff,
                 &W[(size_t)(n0 + row) * CDIM + k0 + seg * 8]);
        }
        asm volatile("cp.async.commit_group;\n");
    };

    fill(0, 0);
    fill(64, 1);
    for (int j = 0; j < 8; j++) {
        if (j < 7) asm volatile("cp.async.wait_group 1;\n");
        else       asm volatile("cp.async.wait_group 0;\n");
        __syncthreads();
        if (j + 2 < 8) fill((j + 2) * 64, (j + 2) % 3);

        int st = (j % 3) * GH_STAGE;
        uint32_t a_base = smem_u32 + (uint32_t)(st + a_term) * 2u;
        uint32_t b_base = smem_u32 + (uint32_t)(GH_B_OFF + st + b_term) * 2u;
        #pragma unroll
        for (int kk = 0; kk < 64; kk += 16) {
            uint32_t afr[4][4], bfr[8][2];
            #pragma unroll
            for (int mi = 0; mi < 4; mi++)
                ldsm4(afr[mi], a_base + (uint32_t)(mi * 16 * 72 + kk) * 2u);
            #pragma unroll
            for (int jp = 0; jp < 4; jp++) {
                uint32_t bb[4];
                ldsm4(bb, b_base + (uint32_t)(jp * 16 * 72 + kk) * 2u);
                bfr[2 * jp][0] = bb[0]; bfr[2 * jp][1] = bb[1];
                bfr[2 * jp + 1][0] = bb[2]; bfr[2 * jp + 1][1] = bb[3];
            }
            #pragma unroll
            for (int mi = 0; mi < 4; mi++)
                #pragma unroll
                for (int ni = 0; ni < 8; ni++)
                    mma_f16(acc[mi][ni], afr[mi], bfr[ni]);
        }
    }

    #pragma unroll
    for (int mi = 0; mi < 4; mi++) {
        #pragma unroll
        for (int ni = 0; ni < 8; ni++) {
            int row = m0 + wm * 64 + mi * 16 + g;
            int col = n0 + wn * 64 + ni * 8 + t4 * 2;
            float b0 = bias[col], b1 = bias[col + 1];
            emit2<MODE>(row,     col, acc[mi][ni][0] + b0, acc[mi][ni][1] + b1, outp);
            emit2<MODE>(row + 8, col, acc[mi][ni][2] + b0, acc[mi][ni][3] + b1, outp);
        }
    }
}

// ================= attention: tensor-core, one CTA per (block, head) ==========
// 128 threads (4 warps). P stays in registers; V fed via ldmatrix.trans.
// smem bytes:
//   ba   fp16 4160        @0      (8320)
//   q    fp16 64x72       @8320   (9216)
//   k    fp16 80x72       @17536  (11520)  rows 65..79 zero
//   v    fp16 80x72       @29056  (11520)  rows 65..79 zero (row-major [key][d])
#define AT_SMEM_BYTES 40576

__global__ void __launch_bounds__(128, 5) attn_kernel() {
    extern __shared__ char smc[];
    __half* ba_s = reinterpret_cast<__half*>(smc);
    __half* q_s  = reinterpret_cast<__half*>(smc + 8320);
    __half* k_s  = reinterpret_cast<__half*>(smc + 17536);
    __half* v_s  = reinterpret_cast<__half*>(smc + 29056);

    int bid = blockIdx.x;      // 0..1023
    int h   = blockIdx.y;      // 0..7
    int tid = threadIdx.x;

    {
        const uint32_t* src = reinterpret_cast<const uint32_t*>(g_biasadd + (size_t)bid * 4160);
        uint32_t* dst = reinterpret_cast<uint32_t*>(ba_s);
        for (int i = tid; i < 2080; i += 128) dst[i] = src[i];
    }
    const __half2* qg = reinterpret_cast<const __half2*>(g_qh + (size_t)(bid * 64) * CDIM + h * 64);
    for (int i = tid; i < 64 * 32; i += 128) {
        int row = i >> 5, c = i & 31;
        *reinterpret_cast<__half2*>(&q_s[row * 72 + c * 2]) = qg[row * 256 + c];
    }
    const __half2* kg = reinterpret_cast<const __half2*>(g_kh + (size_t)(bid * 65) * CDIM + h * 64);
    const __half2* vg = reinterpret_cast<const __half2*>(g_vh + (size_t)(bid * 65) * CDIM + h * 64);
    for (int i = tid; i < 65 * 32; i += 128) {
        int row = i >> 5, c = i & 31;
        *reinterpret_cast<__half2*>(&k_s[row * 72 + c * 2]) = kg[row * 256 + c];
        *reinterpret_cast<__half2*>(&v_s[row * 72 + c * 2]) = vg[row * 256 + c];
    }
    // zero pad rows 65..79 of k and v (15 rows x 72 halves = 540 words each)
    for (int i = tid; i < 540; i += 128) {
        reinterpret_cast<uint32_t*>(k_s + 65 * 72)[i] = 0u;
        reinterpret_cast<uint32_t*>(v_s + 65 * 72)[i] = 0u;
    }
    __syncthreads();

    int lane = tid & 31, w = tid >> 5;
    int g = lane >> 2, t4 = lane & 3;
    int r0 = w * 16;

    uint32_t q_u32 = (uint32_t)__cvta_generic_to_shared(q_s);
    uint32_t k_u32 = (uint32_t)__cvta_generic_to_shared(k_s);
    uint32_t v_u32 = (uint32_t)__cvta_generic_to_shared(v_s);

    uint32_t qa_base = q_u32 + (uint32_t)(((r0 + (lane & 15)) * 72 + (lane >> 4) * 8) * 2);
    uint32_t kb_term = (uint32_t)((((lane >> 4) * 8 + (lane & 7)) * 72 + ((lane >> 3) & 1) * 8) * 2);
    uint32_t vb_term = (uint32_t)(((lane & 15) * 72 + (lane >> 4) * 8) * 2);

    // ---- scores: S[r0..r0+15][0..79] ----
    float acc[10][4];
    #pragma unroll
    for (int nt = 0; nt < 10; nt++)
        #pragma unroll
        for (int r = 0; r < 4; r++) acc[nt][r] = 0.f;

    #pragma unroll
    for (int kst = 0; kst < 4; kst++) {
        uint32_t a[4];
        ldsm4(a, qa_base + (uint32_t)(kst * 16 * 2));
        #pragma unroll
        for (int jp = 0; jp < 5; jp++) {
            uint32_t bb[4];
            ldsm4(bb, k_u32 + kb_term + (uint32_t)((jp * 16 * 72 + kst * 16) * 2));
            mma_f16(acc[2 * jp], a, bb);
            mma_f16(acc[2 * jp + 1], a, bb + 2);
        }
    }

    // ---- softmax + lew on fragments; P packed straight into registers ----
    const __half* lewp = g_lewh + ((size_t)bid * NH + h) * 4160;
    uint32_t ph[2][10];
    #pragma unroll
    for (int rr = 0; rr < 2; rr++) {
        int row = r0 + g + rr * 8;
        float mx = -1e30f;
        #pragma unroll
        for (int nt = 0; nt < 10; nt++) {
            #pragma unroll
            for (int e = 0; e < 2; e++) {
                int col = nt * 8 + t4 * 2 + e;
                float s = (col < 65) ? fmaf(acc[nt][rr * 2 + e], 0.125f,
                                            __half2float(ba_s[row * 65 + col]))
                                     : -1e30f;
                acc[nt][rr * 2 + e] = s;
                mx = fmaxf(mx, s);
            }
        }
        mx = fmaxf(mx, __shfl_xor_sync(0xffffffffu, mx, 1));
        mx = fmaxf(mx, __shfl_xor_sync(0xffffffffu, mx, 2));
        float sum = 0.f;
        #pragma unroll
        for (int nt = 0; nt < 10; nt++) {
            #pragma unroll
            for (int e = 0; e < 2; e++) {
                float p = __expf(acc[nt][rr * 2 + e] - mx);
                acc[nt][rr * 2 + e] = p;
                sum += p;
            }
        }
        sum += __shfl_xor_sync(0xffffffffu, sum, 1);
        sum += __shfl_xor_sync(0xffffffffu, sum, 2);
        float inv = 1.f / sum;
        #pragma unroll
        for (int nt = 0; nt < 10; nt++) {
            int col = nt * 8 + t4 * 2;
            float c0 = (col < 65)     ? fmaf(acc[nt][rr * 2],     inv, __half2float(__ldg(&lewp[row * 65 + col])))     : 0.f;
            float c1 = (col + 1 < 65) ? fmaf(acc[nt][rr * 2 + 1], inv, __half2float(__ldg(&lewp[row * 65 + col + 1]))) : 0.f;
            __half2 t = __floats2half2_rn(c0, c1);
            ph[rr][nt] = *reinterpret_cast<uint32_t*>(&t);
        }
    }

    // ---- AV: O[r0..r0+15][0..63] = P[.,0..79] x V[0..79,.] (B via ldmatrix.trans) ----
    float oc[8][4];
    #pragma unroll
    for (int nt = 0; nt < 8; nt++)
        #pragma unroll
        for (int r = 0; r < 4; r++) oc[nt][r] = 0.f;

    #pragma unroll
    for (int kst = 0; kst < 5; kst++) {
        uint32_t a2[4] = { ph[0][2 * kst], ph[1][2 * kst],
                           ph[0][2 * kst + 1], ph[1][2 * kst + 1] };
        #pragma unroll
        for (int jp = 0; jp < 4; jp++) {
            uint32_t bb[4];
            ldsm4t(bb, v_u32 + vb_term + (uint32_t)((kst * 16 * 72 + jp * 16) * 2));
            mma_f16(oc[2 * jp], a2, bb);
            mma_f16(oc[2 * jp + 1], a2, bb + 2);
        }
    }

    __half* og = g_atth + (size_t)(bid * 64) * CDIM + h * 64;
    #pragma unroll
    for (int nt = 0; nt < 8; nt++) {
        int col = nt * 8 + t4 * 2;
        *reinterpret_cast<__half2*>(&og[(size_t)(r0 + g) * CDIM + col]) =
            __floats2half2_rn(oc[nt][0], oc[nt][1]);
        *reinterpret_cast<__half2*>(&og[(size_t)(r0 + g + 8) * CDIM + col]) =
            __floats2half2_rn(oc[nt][2], oc[nt][3]);
    }
}

// ================= host =================
extern "C" void kernel_launch(void* const* d_in, const int* in_sizes, int n_in,
                              void* d_out, int out_size) {
    (void)in_sizes; (void)n_in; (void)out_size;
    const float* x      = (const float*)d_in[0];
    const int*   amask  = (const int*)d_in[1];
    const float* edge   = (const float*)d_in[2];
    const float* qkv_w  = (const float*)d_in[3];
    const float* qkv_b  = (const float*)d_in[4];
    const float* proj_w = (const float*)d_in[5];
    const float* proj_b = (const float*)d_in[6];
    const float* eg_w   = (const float*)d_in[7];
    const float* eg_b   = (const float*)d_in[8];
    float* out = (float*)d_out;

    cudaFuncSetAttribute(attn_kernel, cudaFuncAttributeMaxDynamicSharedMemorySize, AT_SMEM_BYTES);
    cudaFuncSetAttribute(gemm_h<0>, cudaFuncAttributeMaxDynamicSharedMemorySize, GEMM_SMEM_BYTES);
    cudaFuncSetAttribute(gemm_h<1>, cudaFuncAttributeMaxDynamicSharedMemorySize, GEMM_SMEM_BYTES);
    cudaFuncSetAttribute(gemm_h<2>, cudaFuncAttributeMaxDynamicSharedMemorySize, GEMM_SMEM_BYTES);

    __half* d_xh;  cudaGetSymbolAddress((void**)&d_xh,  g_xh);
    __half* d_wqh; cudaGetSymbolAddress((void**)&d_wqh, g_wqh);
    __half* d_wph; cudaGetSymbolAddress((void**)&d_wph, g_wph);

    conv_h<<<(3 * CDIM * CDIM / 4 + 255) / 256, 256>>>((const float4*)qkv_w, (__half2*)d_wqh, 3 * CDIM * CDIM / 4);
    conv_h<<<(CDIM * CDIM / 4 + 255) / 256, 256>>>((const float4*)proj_w, (__half2*)d_wph, CDIM * CDIM / 4);

    mean_conv_kernel<<<BNB, 256>>>(x);
    prep_kernel<<<dim3(BNB, 2), 256>>>(edge, amask, eg_w, eg_b);

    gemm_h<0><<<dim3(1536 / 128, MX / 128), 128, GEMM_SMEM_BYTES>>>(d_xh, d_wqh, qkv_b, nullptr);
    gemm_h<1><<<dim3(1024 / 128, BNB / 128), 128, GEMM_SMEM_BYTES>>>(nullptr, d_wqh + (size_t)CDIM * CDIM, qkv_b + CDIM, nullptr);
    attn_kernel<<<dim3(BNB, NH), 128, AT_SMEM_BYTES>>>();
    gemm_h<2><<<dim3(512 / 128, MX / 128), 128, GEMM_SMEM_BYTES>>>(nullptr, d_wph, proj_b, out);
}

// round 11
// speedup vs baseline: 2.0407x; 1.0107x over previous
#include <cuda_runtime.h>
#include <cuda_fp16.h>
#include <cstdint>

#define NB_B   2
#define NB     512
#define LQ     64
#define KEYN   65
#define NH     8
#define HD     64
#define CDIM   512
#define NTOK   32768
#define BNB    (NB_B*NB)        // 1024 blocks total
#define MX     (NB_B*NTOK)      // 65536 x-rows
#define KVROWS (BNB*KEYN)       // 66560 kv-rows

// -------- device scratch (static, allocation-guard safe) --------
__device__ __half g_biasadd[(size_t)BNB*4160];   // fp16 pre-masked additive bias
__device__ __half g_lewh[(size_t)BNB*NH*4160];   // fp16 lew
__device__ __half g_xh [(size_t)MX*CDIM];        // fp16 x
__device__ __half g_wqh[(size_t)3*CDIM*CDIM];    // fp16 qkv_w
__device__ __half g_wph[(size_t)CDIM*CDIM];      // fp16 proj_w
__device__ __half g_bmh[(size_t)BNB*CDIM];       // fp16 block means
__device__ __half g_qh [(size_t)MX*CDIM];        // fp16 q
__device__ __half g_kh [(size_t)KVROWS*CDIM];    // fp16 k
__device__ __half g_vh [(size_t)KVROWS*CDIM];    // fp16 v
__device__ __half g_atth[(size_t)MX*CDIM];       // fp16 attention output

// ================= fp32 -> fp16 conversion (weights only) =================
__global__ void conv_h(const float4* __restrict__ src, __half2* __restrict__ dst, int n4) {
    int i = blockIdx.x * blockDim.x + threadIdx.x;
    if (i < n4) {
        float4 v = src[i];
        dst[2 * i]     = __floats2half2_rn(v.x, v.y);
        dst[2 * i + 1] = __floats2half2_rn(v.z, v.w);
    }
}

// ======== block mean + x->fp16 in one pass over x ========
__global__ void mean_conv_kernel(const float* __restrict__ x) {
    int blk = blockIdx.x;
    const float* base = x + (size_t)blk * (LQ * CDIM);
    __half* xout = g_xh + (size_t)blk * (LQ * CDIM);
    for (int c = threadIdx.x; c < CDIM; c += blockDim.x) {
        float s = 0.f;
        #pragma unroll 8
        for (int l = 0; l < LQ; l++) {
            float v = base[(size_t)l * CDIM + c];
            s += v;
            xout[(size_t)l * CDIM + c] = __float2half_rn(v);
        }
        g_bmh[(size_t)blk * CDIM + c] = __float2half_rn(s * (1.f / 64.f));
    }
}

// ================= prep: fold mask into bias, precompute lew =================
__global__ void __launch_bounds__(256) prep_kernel(const float* __restrict__ edge,
                                                   const int* __restrict__ amask,
                                                   const float* __restrict__ eg_w,
                                                   const float* __restrict__ eg_b) {
    int bid = blockIdx.x;
    int base = blockIdx.y * 2080;
    const float4* e4 = reinterpret_cast<const float4*>(edge) + (size_t)bid * 4160;
    const int* mk = amask + (size_t)bid * 4160;
    float w[NH][4], b[NH];
    #pragma unroll
    for (int h = 0; h < NH; h++) {
        w[h][0] = eg_w[h * 4 + 0]; w[h][1] = eg_w[h * 4 + 1];
        w[h][2] = eg_w[h * 4 + 2]; w[h][3] = eg_w[h * 4 + 3];
        b[h] = eg_b[h];
    }
    for (int i = base + threadIdx.x; i < base + 2080; i += 256) {
        int q = i / 65;
        int k = i - q * 65;
        float4 e = e4[i];
        if (k == 64 || k == q) e = make_float4(0.f, 0.f, 0.f, 1.f);
        bool m = (mk[i] != 0);
        g_biasadd[(size_t)bid * 4160 + i] = __float2half_rn(m ? e.w : -30000.f);
        #pragma unroll
        for (int h = 0; h < NH; h++) {
            float lv = e.x * w[h][0] + e.y * w[h][1] + e.z * w[h][2] + e.w * w[h][3] + b[h];
            g_lewh[((size_t)bid * NH + h) * 4160 + i] = __float2half_rn(m ? lv : 0.f);
        }
    }
}

// ================= mma / ldmatrix helpers =================
__device__ __forceinline__ void mma_f16(float* c, const uint32_t* a, const uint32_t* b) {
    asm volatile(
        "mma.sync.aligned.m16n8k16.row.col.f32.f16.f16.f32 "
        "{%0,%1,%2,%3}, {%4,%5,%6,%7}, {%8,%9}, {%0,%1,%2,%3};\n"
        : "+f"(c[0]), "+f"(c[1]), "+f"(c[2]), "+f"(c[3])
        : "r"(a[0]), "r"(a[1]), "r"(a[2]), "r"(a[3]),
          "r"(b[0]), "r"(b[1]));
}

__device__ __forceinline__ void ldsm4(uint32_t* r, uint32_t addr) {
    asm volatile("ldmatrix.sync.aligned.m8n8.x4.shared.b16 {%0,%1,%2,%3}, [%4];"
                 : "=r"(r[0]), "=r"(r[1]), "=r"(r[2]), "=r"(r[3]) : "r"(addr));
}

__device__ __forceinline__ void ldsm4t(uint32_t* r, uint32_t addr) {
    asm volatile("ldmatrix.sync.aligned.m8n8.x4.trans.shared.b16 {%0,%1,%2,%3}, [%4];"
                 : "=r"(r[0]), "=r"(r[1]), "=r"(r[2]), "=r"(r[3]) : "r"(addr));
}

__device__ __forceinline__ void cp16(uint32_t smem_dst, const __half* gmem_src) {
    asm volatile("cp.async.cg.shared.global [%0], [%1], 16;\n"
                 :: "r"(smem_dst), "l"(gmem_src));
}

// epilogue scatter (column pairs)
template <int MODE>
__device__ __forceinline__ void emit2(int row, int col, float v0, float v1, float* outp) {
    if (MODE == 2) {
        float2 f = make_float2(v0, v1);
        *reinterpret_cast<float2*>(&outp[(size_t)row * CDIM + col]) = f;
    } else {
        __half2 hv = __floats2half2_rn(v0, v1);
        if (MODE == 0) {
            if (col < CDIM) {
                *reinterpret_cast<__half2*>(&g_qh[(size_t)row * CDIM + col]) = hv;
            } else {
                size_t kvr = (size_t)((row >> 6) * KEYN + (row & 63));
                if (col < 2 * CDIM)
                    *reinterpret_cast<__half2*>(&g_kh[kvr * CDIM + (col - CDIM)]) = hv;
                else
                    *reinterpret_cast<__half2*>(&g_vh[kvr * CDIM + (col - 2 * CDIM)]) = hv;
            }
        } else {
            size_t r = (size_t)row * KEYN + (KEYN - 1);
            if (col < CDIM) *reinterpret_cast<__half2*>(&g_kh[r * CDIM + col]) = hv;
            else            *reinterpret_cast<__half2*>(&g_vh[r * CDIM + (col - CDIM)]) = hv;
        }
    }
}

// ================= fp16 GEMM: C = A[M,512] * W[N,512]^T + bias =================
// CTA tile 128x128, 128 threads = 4 warps (2x2), warp tile 64x64.
// k-tile 64 halves, 3-stage cp.async pipeline, 2 CTAs/SM.
#define GH_STAGE  (128 * 72)
#define GH_B_OFF  (3 * GH_STAGE)
#define GEMM_SMEM_BYTES (6 * GH_STAGE * 2)   // 110592 B

template <int MODE>
__global__ void __launch_bounds__(128, 2) gemm_h(const __half* __restrict__ Ain,
                                                 const __half* __restrict__ W,
                                                 const float* __restrict__ bias,
                                                 float* __restrict__ outp) {
    const __half* A = (MODE == 1) ? g_bmh : (MODE == 2 ? g_atth : Ain);
    extern __shared__ __align__(16) __half hsm[];
    uint32_t smem_u32 = (uint32_t)__cvta_generic_to_shared(hsm);

    int tid = threadIdx.x;
    int n0 = blockIdx.x * 128;
    int m0 = blockIdx.y * 128;

    int lane = tid & 31, wid = tid >> 5;
    int wm = wid >> 1, wn = wid & 1;
    int g = lane >> 2, t4 = lane & 3;

    int a_term = (wm * 64 + (lane & 15)) * 72 + (lane >> 4) * 8;
    int b_term = (wn * 64 + (lane >> 4) * 8 + (lane & 7)) * 72 + ((lane >> 3) & 1) * 8;

    float acc[4][8][4];
    #pragma unroll
    for (int mi = 0; mi < 4; mi++)
        #pragma unroll
        for (int ni = 0; ni < 8; ni++)
            #pragma unroll
            for (int r = 0; r < 4; r++) acc[mi][ni][r] = 0.f;

    auto fill = [&](int k0, int st) {
        #pragma unroll
        for (int i = 0; i < 8; i++) {
            int o = tid + 128 * i;
            int row = o >> 3, seg = o & 7;
            uint32_t doff = (uint32_t)(st * GH_STAGE + row * 72 + seg * 8) * 2u;
            cp16(smem_u32 + doff, &A[(size_t)(m0 + row) * CDIM + k0 + seg * 8]);
            cp16(smem_u32 + (uint32_t)GH_B_OFF * 2u + doff,
                 &W[(size_t)(n0 + row) * CDIM + k0 + seg * 8]);
        }
        asm volatile("cp.async.commit_group;\n");
    };

    fill(0, 0);
    fill(64, 1);
    for (int j = 0; j < 8; j++) {
        if (j < 7) asm volatile("cp.async.wait_group 1;\n");
        else       asm volatile("cp.async.wait_group 0;\n");
        __syncthreads();
        if (j + 2 < 8) fill((j + 2) * 64, (j + 2) % 3);

        int st = (j % 3) * GH_STAGE;
        uint32_t a_base = smem_u32 + (uint32_t)(st + a_term) * 2u;
        uint32_t b_base = smem_u32 + (uint32_t)(GH_B_OFF + st + b_term) * 2u;
        #pragma unroll
        for (int kk = 0; kk < 64; kk += 16) {
            uint32_t afr[4][4], bfr[8][2];
            #pragma unroll
            for (int mi = 0; mi < 4; mi++)
                ldsm4(afr[mi], a_base + (uint32_t)(mi * 16 * 72 + kk) * 2u);
            #pragma unroll
            for (int jp = 0; jp < 4; jp++) {
                uint32_t bb[4];
                ldsm4(bb, b_base + (uint32_t)(jp * 16 * 72 + kk) * 2u);
                bfr[2 * jp][0] = bb[0]; bfr[2 * jp][1] = bb[1];
                bfr[2 * jp + 1][0] = bb[2]; bfr[2 * jp + 1][1] = bb[3];
            }
            #pragma unroll
            for (int mi = 0; mi < 4; mi++)
                #pragma unroll
                for (int ni = 0; ni < 8; ni++)
                    mma_f16(acc[mi][ni], afr[mi], bfr[ni]);
        }
    }

    #pragma unroll
    for (int mi = 0; mi < 4; mi++) {
        #pragma unroll
        for (int ni = 0; ni < 8; ni++) {
            int row = m0 + wm * 64 + mi * 16 + g;
            int col = n0 + wn * 64 + ni * 8 + t4 * 2;
            float b0 = bias[col], b1 = bias[col + 1];
            emit2<MODE>(row,     col, acc[mi][ni][0] + b0, acc[mi][ni][1] + b1, outp);
            emit2<MODE>(row + 8, col, acc[mi][ni][2] + b0, acc[mi][ni][3] + b1, outp);
        }
    }
}

// ================= attention: tensor-core, one CTA per (block, head) ==========
// 128 threads (4 warps). P stays in registers; V fed via ldmatrix.trans.
// smem bytes:
//   ba   fp16 4160        @0      (8320)
//   q    fp16 64x72       @8320   (9216)
//   k    fp16 80x72       @17536  (11520)  rows 65..79 zero
//   v    fp16 80x72       @29056  (11520)  rows 65..79 zero (row-major [key][d])
#define AT_SMEM_BYTES 40576

__global__ void __launch_bounds__(128, 5) attn_kernel() {
    extern __shared__ char smc[];
    __half* ba_s = reinterpret_cast<__half*>(smc);
    __half* q_s  = reinterpret_cast<__half*>(smc + 8320);
    __half* k_s  = reinterpret_cast<__half*>(smc + 17536);
    __half* v_s  = reinterpret_cast<__half*>(smc + 29056);

    int bid = blockIdx.x;      // 0..1023
    int h   = blockIdx.y;      // 0..7
    int tid = threadIdx.x;

    {
        const uint32_t* src = reinterpret_cast<const uint32_t*>(g_biasadd + (size_t)bid * 4160);
        uint32_t* dst = reinterpret_cast<uint32_t*>(ba_s);
        for (int i = tid; i < 2080; i += 128) dst[i] = src[i];
    }
    const __half2* qg = reinterpret_cast<const __half2*>(g_qh + (size_t)(bid * 64) * CDIM + h * 64);
    for (int i = tid; i < 64 * 32; i += 128) {
        int row = i >> 5, c = i & 31;
        *reinterpret_cast<__half2*>(&q_s[row * 72 + c * 2]) = qg[row * 256 + c];
    }
    const __half2* kg = reinterpret_cast<const __half2*>(g_kh + (size_t)(bid * 65) * CDIM + h * 64);
    const __half2* vg = reinterpret_cast<const __half2*>(g_vh + (size_t)(bid * 65) * CDIM + h * 64);
    for (int i = tid; i < 65 * 32; i += 128) {
        int row = i >> 5, c = i & 31;
        *reinterpret_cast<__half2*>(&k_s[row * 72 + c * 2]) = kg[row * 256 + c];
        *reinterpret_cast<__half2*>(&v_s[row * 72 + c * 2]) = vg[row * 256 + c];
    }
    // zero pad rows 65..79 of k and v (15 rows x 72 halves = 540 words each)
    for (int i = tid; i < 540; i += 128) {
        reinterpret_cast<uint32_t*>(k_s + 65 * 72)[i] = 0u;
        reinterpret_cast<uint32_t*>(v_s + 65 * 72)[i] = 0u;
    }
    __syncthreads();

    int lane = tid & 31, w = tid >> 5;
    int g = lane >> 2, t4 = lane & 3;
    int r0 = w * 16;

    uint32_t q_u32 = (uint32_t)__cvta_generic_to_shared(q_s);
    uint32_t k_u32 = (uint32_t)__cvta_generic_to_shared(k_s);
    uint32_t v_u32 = (uint32_t)__cvta_generic_to_shared(v_s);

    uint32_t qa_base = q_u32 + (uint32_t)(((r0 + (lane & 15)) * 72 + (lane >> 4) * 8) * 2);
    uint32_t kb_term = (uint32_t)((((lane >> 4) * 8 + (lane & 7)) * 72 + ((lane >> 3) & 1) * 8) * 2);
    uint32_t vb_term = (uint32_t)(((lane & 15) * 72 + (lane >> 4) * 8) * 2);

    // ---- scores: S[r0..r0+15][0..79] ----
    float acc[10][4];
    #pragma unroll
    for (int nt = 0; nt < 10; nt++)
        #pragma unroll
        for (int r = 0; r < 4; r++) acc[nt][r] = 0.f;

    #pragma unroll
    for (int kst = 0; kst < 4; kst++) {
        uint32_t a[4];
        ldsm4(a, qa_base + (uint32_t)(kst * 16 * 2));
        #pragma unroll
        for (int jp = 0; jp < 5; jp++) {
            uint32_t bb[4];
            ldsm4(bb, k_u32 + kb_term + (uint32_t)((jp * 16 * 72 + kst * 16) * 2));
            mma_f16(acc[2 * jp], a, bb);
            mma_f16(acc[2 * jp + 1], a, bb + 2);
        }
    }

    // ---- softmax + lew on fragments; P packed straight into registers ----
    const __half* lewp = g_lewh + ((size_t)bid * NH + h) * 4160;
    uint32_t ph[2][10];
    #pragma unroll
    for (int rr = 0; rr < 2; rr++) {
        int row = r0 + g + rr * 8;
        float mx = -1e30f;
        #pragma unroll
        for (int nt = 0; nt < 10; nt++) {
            #pragma unroll
            for (int e = 0; e < 2; e++) {
                int col = nt * 8 + t4 * 2 + e;
                float s = (col < 65) ? fmaf(acc[nt][rr * 2 + e], 0.125f,
                                            __half2float(ba_s[row * 65 + col]))
                                     : -1e30f;
                acc[nt][rr * 2 + e] = s;
                mx = fmaxf(mx, s);
            }
        }
        mx = fmaxf(mx, __shfl_xor_sync(0xffffffffu, mx, 1));
        mx = fmaxf(mx, __shfl_xor_sync(0xffffffffu, mx, 2));
        float sum = 0.f;
        #pragma unroll
        for (int nt = 0; nt < 10; nt++) {
            #pragma unroll
            for (int e = 0; e < 2; e++) {
                float p = __expf(acc[nt][rr * 2 + e] - mx);
                acc[nt][rr * 2 + e] = p;
                sum += p;
            }
        }
        sum += __shfl_xor_sync(0xffffffffu, sum, 1);
        sum += __shfl_xor_sync(0xffffffffu, sum, 2);
        float inv = 1.f / sum;
        #pragma unroll
        for (int nt = 0; nt < 10; nt++) {
            int col = nt * 8 + t4 * 2;
            float c0 = (col < 65)     ? fmaf(acc[nt][rr * 2],     inv, __half2float(__ldg(&lewp[row * 65 + col])))     : 0.f;
            float c1 = (col + 1 < 65) ? fmaf(acc[nt][rr * 2 + 1], inv, __half2float(__ldg(&lewp[row * 65 + col + 1]))) : 0.f;
            __half2 t = __floats2half2_rn(c0, c1);
            ph[rr][nt] = *reinterpret_cast<uint32_t*>(&t);
        }
    }

    // ---- AV: O[r0..r0+15][0..63] = P[.,0..79] x V[0..79,.] (B via ldmatrix.trans) ----
    float oc[8][4];
    #pragma unroll
    for (int nt = 0; nt < 8; nt++)
        #pragma unroll
        for (int r = 0; r < 4; r++) oc[nt][r] = 0.f;

    #pragma unroll
    for (int kst = 0; kst < 5; kst++) {
        uint32_t a2[4] = { ph[0][2 * kst], ph[1][2 * kst],
                           ph[0][2 * kst + 1], ph[1][2 * kst + 1] };
        #pragma unroll
        for (int jp = 0; jp < 4; jp++) {
            uint32_t bb[4];
            ldsm4t(bb, v_u32 + vb_term + (uint32_t)((kst * 16 * 72 + jp * 16) * 2));
            mma_f16(oc[2 * jp], a2, bb);
            mma_f16(oc[2 * jp + 1], a2, bb + 2);
        }
    }

    __half* og = g_atth + (size_t)(bid * 64) * CDIM + h * 64;
    #pragma unroll
    for (int nt = 0; nt < 8; nt++) {
        int col = nt * 8 + t4 * 2;
        *reinterpret_cast<__half2*>(&og[(size_t)(r0 + g) * CDIM + col]) =
            __floats2half2_rn(oc[nt][0], oc[nt][1]);
        *reinterpret_cast<__half2*>(&og[(size_t)(r0 + g + 8) * CDIM + col]) =
            __floats2half2_rn(oc[nt][2], oc[nt][3]);
    }
}

// ================= host =================
extern "C" void kernel_launch(void* const* d_in, const int* in_sizes, int n_in,
                              void* d_out, int out_size) {
    (void)in_sizes; (void)n_in; (void)out_size;
    const float* x      = (const float*)d_in[0];
    const int*   amask  = (const int*)d_in[1];
    const float* edge   = (const float*)d_in[2];
    const float* qkv_w  = (const float*)d_in[3];
    const float* qkv_b  = (const float*)d_in[4];
    const float* proj_w = (const float*)d_in[5];
    const float* proj_b = (const float*)d_in[6];
    const float* eg_w   = (const float*)d_in[7];
    const float* eg_b   = (const float*)d_in[8];
    float* out = (float*)d_out;

    cudaFuncSetAttribute(attn_kernel, cudaFuncAttributeMaxDynamicSharedMemorySize, AT_SMEM_BYTES);
    cudaFuncSetAttribute(gemm_h<0>, cudaFuncAttributeMaxDynamicSharedMemorySize, GEMM_SMEM_BYTES);
    cudaFuncSetAttribute(gemm_h<1>, cudaFuncAttributeMaxDynamicSharedMemorySize, GEMM_SMEM_BYTES);
    cudaFuncSetAttribute(gemm_h<2>, cudaFuncAttributeMaxDynamicSharedMemorySize, GEMM_SMEM_BYTES);

    __half* d_xh;  cudaGetSymbolAddress((void**)&d_xh,  g_xh);
    __half* d_wqh; cudaGetSymbolAddress((void**)&d_wqh, g_wqh);
    __half* d_wph; cudaGetSymbolAddress((void**)&d_wph, g_wph);

    conv_h<<<(3 * CDIM * CDIM / 4 + 255) / 256, 256>>>((const float4*)qkv_w, (__half2*)d_wqh, 3 * CDIM * CDIM / 4);
    conv_h<<<(CDIM * CDIM / 4 + 255) / 256, 256>>>((const float4*)proj_w, (__half2*)d_wph, CDIM * CDIM / 4);

    mean_conv_kernel<<<BNB, 256>>>(x);
    prep_kernel<<<dim3(BNB, 2), 256>>>(edge, amask, eg_w, eg_b);

    gemm_h<0><<<dim3(1536 / 128, MX / 128), 128, GEMM_SMEM_BYTES>>>(d_xh, d_wqh, qkv_b, nullptr);
    gemm_h<1><<<dim3(1024 / 128, BNB / 128), 128, GEMM_SMEM_BYTES>>>(nullptr, d_wqh + (size_t)CDIM * CDIM, qkv_b + CDIM, nullptr);
    attn_kernel<<<dim3(BNB, NH), 128, AT_SMEM_BYTES>>>();
    gemm_h<2><<<dim3(512 / 128, MX / 128), 128, GEMM_SMEM_BYTES>>>(nullptr, d_wph, proj_b, out);
}